// round 1
// baseline (speedup 1.0000x reference)
#include <cuda_runtime.h>
#include <math.h>

#define N_NODES 50000
#define N_EDGES 500000
#define C 128
#define G3 384
#define NC (N_NODES*C)

// ---------------- scratch (device globals; no allocations allowed) ----------
__device__ float g_h[NC];
__device__ float g_m[NC];
__device__ float g_x[NC];
__device__ float g_agg[NC];
__device__ float g_tot[NC];
__device__ float g_gi[N_NODES*G3];
__device__ float g_gh[N_NODES*G3];

// ---------------- feature build ---------------------------------------------
__global__ void k_feat(const int* __restrict__ xt, const int* __restrict__ xk,
                       const float* __restrict__ xs, float* __restrict__ h) {
    int i = blockIdx.x;
    int c = threadIdx.x;
    int t = xt[i];
    int k = xk[i];
    k = min(max(k, 0), 93);
    float v;
    if (c < 32)       v = (c == t) ? 1.f : 0.f;
    else if (c < 126) v = ((c - 32) == k) ? 1.f : 0.f;
    else              v = xs[i * 2 + (c - 126)];
    h[(size_t)i * C + c] = v;
}

// ---------------- utility ----------------------------------------------------
__global__ void k_zero(float* __restrict__ p, int n4) {
    int i = blockIdx.x * blockDim.x + threadIdx.x;
    if (i < n4) ((float4*)p)[i] = make_float4(0.f, 0.f, 0.f, 0.f);
}

__global__ void k_copy(float* __restrict__ d, const float* __restrict__ s, int n4) {
    int i = blockIdx.x * blockDim.x + threadIdx.x;
    if (i < n4) ((float4*)d)[i] = ((const float4*)s)[i];
}

// ---------------- GEMM: Y[64 x 128 tile] = A[N,128] x op(B) ------------------
// TB=false: Y[i,j] = sum_k A[i,k] * B[k,j]        (B row-major [128,128])
// TB=true : Y[i,j] = sum_k A[i,k] * B[j,k]        (B row-major [Ncols,128])
// Bs staged k-major [128][132]; inner loop: 1 LDS.128 (B) + 8 broadcast LDS (A)
// per 32 FFMA.
template<bool TB, bool BIAS, bool RELU>
__global__ void k_gemm(const float* __restrict__ A, const float* __restrict__ B,
                       const float* __restrict__ bias, float* __restrict__ Y,
                       int ystride) {
    extern __shared__ float sm[];
    float* As = sm;                // [64][128]
    float* Bs = sm + 64 * 128;     // [128][132]
    const int BS = 132;
    int tid  = threadIdx.x;
    int row0 = blockIdx.x * 64;
    int col0 = blockIdx.y * 128;

    // load A tile (coalesced float4), zero-fill OOB rows
    const float4* A4 = (const float4*)A;
#pragma unroll
    for (int i = 0; i < 8; i++) {
        int idx = tid + i * 256;          // 0..2047
        int r = idx >> 5, kq = idx & 31;
        int grow = row0 + r;
        float4 v = make_float4(0.f, 0.f, 0.f, 0.f);
        if (grow < N_NODES) v = A4[(size_t)grow * 32 + kq];
        ((float4*)(As + r * 128))[kq] = v;
    }
    // load B tile into Bs[k][j]
    const float4* B4 = (const float4*)B;
    if (!TB) {
#pragma unroll
        for (int i = 0; i < 16; i++) {
            int idx = tid + i * 256;      // 0..4095
            int k = idx >> 5, jq = idx & 31;
            float4 v = B4[k * 32 + jq];
            ((float4*)(Bs + k * BS))[jq] = v;
        }
    } else {
#pragma unroll
        for (int i = 0; i < 16; i++) {
            int idx = tid + i * 256;
            int j = idx & 127, kq = idx >> 7;   // kq 0..31
            float4 v = B4[(size_t)(col0 + j) * 32 + kq];
            Bs[(kq * 4 + 0) * BS + j] = v.x;
            Bs[(kq * 4 + 1) * BS + j] = v.y;
            Bs[(kq * 4 + 2) * BS + j] = v.z;
            Bs[(kq * 4 + 3) * BS + j] = v.w;
        }
    }
    __syncthreads();

    int warp = tid >> 5, lane = tid & 31;
    int r0 = warp * 8;      // 8 rows per warp (broadcast A loads)
    int c0 = lane * 4;      // 4 cols per lane
    float acc[8][4];
#pragma unroll
    for (int rr = 0; rr < 8; rr++)
#pragma unroll
        for (int q = 0; q < 4; q++) acc[rr][q] = 0.f;

#pragma unroll 8
    for (int k = 0; k < 128; k++) {
        float4 b = *(const float4*)(Bs + k * BS + c0);
#pragma unroll
        for (int rr = 0; rr < 8; rr++) {
            float a = As[(r0 + rr) * 128 + k];
            acc[rr][0] += a * b.x;
            acc[rr][1] += a * b.y;
            acc[rr][2] += a * b.z;
            acc[rr][3] += a * b.w;
        }
    }

    float4 bi = make_float4(0.f, 0.f, 0.f, 0.f);
    if (BIAS) bi = *(const float4*)(bias + col0 + c0);
#pragma unroll
    for (int rr = 0; rr < 8; rr++) {
        int grow = row0 + r0 + rr;
        if (grow < N_NODES) {
            float4 o;
            o.x = acc[rr][0] + bi.x;
            o.y = acc[rr][1] + bi.y;
            o.z = acc[rr][2] + bi.z;
            o.w = acc[rr][3] + bi.w;
            if (RELU) {
                o.x = fmaxf(o.x, 0.f); o.y = fmaxf(o.y, 0.f);
                o.z = fmaxf(o.z, 0.f); o.w = fmaxf(o.w, 0.f);
            }
            *(float4*)(Y + (size_t)grow * ystride + col0 + c0) = o;
        }
    }
}

// ---------------- scatter-add: agg[dst] += x[src] for edges of type t --------
__global__ void k_scatter(const float* __restrict__ x, const int* __restrict__ ei,
                          const int* __restrict__ et, int t, float* __restrict__ agg) {
    int gid = blockIdx.x * blockDim.x + threadIdx.x;
    int e = gid >> 5;
    int lane = gid & 31;
    if (e >= N_EDGES) return;
    if (et[e] != t) return;
    int s = ei[e];
    int d = ei[N_EDGES + e];
    float4 v = ((const float4*)(x + (size_t)s * C))[lane];
    float* dst = agg + (size_t)d * C + lane * 4;
    atomicAdd(dst + 0, v.x);
    atomicAdd(dst + 1, v.y);
    atomicAdd(dst + 2, v.z);
    atomicAdd(dst + 3, v.w);
}

// ---------------- GRU gates (gi/gh already have biases) ----------------------
__global__ void k_gru(const float* __restrict__ gi, const float* __restrict__ gh,
                      float* __restrict__ m, float* __restrict__ tot, int addTot) {
    int idx = blockIdx.x * blockDim.x + threadIdx.x;
    if (idx >= NC) return;
    int row = idx >> 7;
    int j = idx & 127;
    const float* gir = gi + (size_t)row * G3;
    const float* ghr = gh + (size_t)row * G3;
    float r = 1.f / (1.f + __expf(-(gir[j] + ghr[j])));
    float z = 1.f / (1.f + __expf(-(gir[128 + j] + ghr[128 + j])));
    float n = tanhf(gir[256 + j] + r * ghr[256 + j]);
    float mv = m[idx];
    float o = (1.f - z) * n + z * mv;
    m[idx] = o;
    if (addTot) tot[idx] += o;
}

// ---------------- LayerNorm(h+tot)*g+b, ReLU (warp per node) -----------------
__global__ void k_ln(float* __restrict__ h, const float* __restrict__ tot,
                     const float* __restrict__ g, const float* __restrict__ b) {
    int i = blockIdx.x * 8 + (threadIdx.x >> 5);
    int lane = threadIdx.x & 31;
    if (i >= N_NODES) return;
    float4 hv = ((float4*)(h + (size_t)i * C))[lane];
    float4 tv = ((const float4*)(tot + (size_t)i * C))[lane];
    float4 v = make_float4(hv.x + tv.x, hv.y + tv.y, hv.z + tv.z, hv.w + tv.w);
    float s  = v.x + v.y + v.z + v.w;
    float ss = v.x * v.x + v.y * v.y + v.z * v.z + v.w * v.w;
#pragma unroll
    for (int off = 16; off; off >>= 1) {
        s  += __shfl_xor_sync(0xffffffffu, s, off);
        ss += __shfl_xor_sync(0xffffffffu, ss, off);
    }
    float mu  = s * (1.f / 128.f);
    float var = ss * (1.f / 128.f) - mu * mu;
    float inv = rsqrtf(var + 1e-5f);
    float4 gg = ((const float4*)g)[lane];
    float4 bb = ((const float4*)b)[lane];
    float4 o;
    o.x = fmaxf((v.x - mu) * inv * gg.x + bb.x, 0.f);
    o.y = fmaxf((v.y - mu) * inv * gg.y + bb.y, 0.f);
    o.z = fmaxf((v.z - mu) * inv * gg.z + bb.z, 0.f);
    o.w = fmaxf((v.w - mu) * inv * gg.w + bb.w, 0.f);
    ((float4*)(h + (size_t)i * C))[lane] = o;
}

// ---------------- head second layer (warp per node) --------------------------
__global__ void k_head2(const float* __restrict__ z, const float* __restrict__ w2,
                        const float* __restrict__ b2, float* __restrict__ out) {
    int i = blockIdx.x * 8 + (threadIdx.x >> 5);
    int lane = threadIdx.x & 31;
    if (i >= N_NODES) return;
    float4 zv = ((const float4*)(z + (size_t)i * C))[lane];
    float4 w0 = ((const float4*)w2)[lane];
    float4 w1 = ((const float4*)(w2 + C))[lane];
    float d0 = zv.x * w0.x + zv.y * w0.y + zv.z * w0.z + zv.w * w0.w;
    float d1 = zv.x * w1.x + zv.y * w1.y + zv.z * w1.z + zv.w * w1.w;
#pragma unroll
    for (int off = 16; off; off >>= 1) {
        d0 += __shfl_xor_sync(0xffffffffu, d0, off);
        d1 += __shfl_xor_sync(0xffffffffu, d1, off);
    }
    if (lane == 0) {
        out[(size_t)i * 2 + 0] = d0 + b2[0];
        out[(size_t)i * 2 + 1] = d1 + b2[1];
    }
}

// ---------------- driver -----------------------------------------------------
extern "C" void kernel_launch(void* const* d_in, const int* in_sizes, int n_in,
                              void* d_out, int out_size) {
    const int*   x_type     = (const int*)d_in[0];
    const int*   x_tok      = (const int*)d_in[1];
    const float* x_small    = (const float*)d_in[2];
    const int*   edge_index = (const int*)d_in[3];
    const int*   edge_type  = (const int*)d_in[4];
    const float* conv_w     = (const float*)d_in[5];   // [2,3,3,128,128]
    const float* gru_wih    = (const float*)d_in[6];   // [2,3,384,128]
    const float* gru_whh    = (const float*)d_in[7];
    const float* gru_bih    = (const float*)d_in[8];   // [2,3,384]
    const float* gru_bhh    = (const float*)d_in[9];
    const float* ln_g       = (const float*)d_in[10];  // [2,128]
    const float* ln_b       = (const float*)d_in[11];
    const float* head_w1    = (const float*)d_in[12];  // [128,128]
    const float* head_b1    = (const float*)d_in[13];
    const float* head_w2    = (const float*)d_in[14];  // [2,128]
    const float* head_b2    = (const float*)d_in[15];
    float* out = (float*)d_out;

    float *ph, *pm, *px, *pagg, *ptot, *pgi, *pgh;
    cudaGetSymbolAddress((void**)&ph,   g_h);
    cudaGetSymbolAddress((void**)&pm,   g_m);
    cudaGetSymbolAddress((void**)&px,   g_x);
    cudaGetSymbolAddress((void**)&pagg, g_agg);
    cudaGetSymbolAddress((void**)&ptot, g_tot);
    cudaGetSymbolAddress((void**)&pgi,  g_gi);
    cudaGetSymbolAddress((void**)&pgh,  g_gh);

    const size_t smem = (64 * 128 + 128 * 132) * sizeof(float);  // 100352 B
    cudaFuncSetAttribute(k_gemm<false, false, false>,
                         cudaFuncAttributeMaxDynamicSharedMemorySize, (int)smem);
    cudaFuncSetAttribute(k_gemm<true, true, false>,
                         cudaFuncAttributeMaxDynamicSharedMemorySize, (int)smem);
    cudaFuncSetAttribute(k_gemm<true, true, true>,
                         cudaFuncAttributeMaxDynamicSharedMemorySize, (int)smem);

    const int rowBlocks = (N_NODES + 63) / 64;      // 782
    const int n4 = NC / 4;
    const int zgrid = (n4 + 255) / 256;
    const int warpGrid = (N_NODES + 7) / 8;

    k_feat<<<N_NODES, 128>>>(x_type, x_tok, x_small, ph);

    for (int b = 0; b < 2; b++) {
        k_zero<<<zgrid, 256>>>(ptot, n4);
        for (int t = 0; t < 3; t++) {
            k_copy<<<zgrid, 256>>>(pm, ph, n4);
            for (int s = 0; s < 3; s++) {
                const float* Wc = conv_w + (size_t)(((b * 3 + t) * 3 + s)) * C * C;
                k_gemm<false, false, false><<<dim3(rowBlocks, 1), 256, smem>>>(
                    pm, Wc, nullptr, px, C);

                k_zero<<<zgrid, 256>>>(pagg, n4);
                k_scatter<<<(N_EDGES * 32) / 256, 256>>>(px, edge_index, edge_type, t, pagg);

                const float* Wih = gru_wih + (size_t)(b * 3 + t) * G3 * C;
                const float* Bih = gru_bih + (size_t)(b * 3 + t) * G3;
                k_gemm<true, true, false><<<dim3(rowBlocks, 3), 256, smem>>>(
                    pagg, Wih, Bih, pgi, G3);

                const float* Whh = gru_whh + (size_t)(b * 3 + t) * G3 * C;
                const float* Bhh = gru_bhh + (size_t)(b * 3 + t) * G3;
                k_gemm<true, true, false><<<dim3(rowBlocks, 3), 256, smem>>>(
                    pm, Whh, Bhh, pgh, G3);

                k_gru<<<(NC + 255) / 256, 256>>>(pgi, pgh, pm, ptot, (s == 2) ? 1 : 0);
            }
        }
        k_ln<<<warpGrid, 256>>>(ph, ptot, ln_g + b * C, ln_b + b * C);
    }

    // head: z = relu(h @ w1.T + b1) into g_x, then 2-col projection
    k_gemm<true, true, true><<<dim3(rowBlocks, 1), 256, smem>>>(
        ph, head_w1, head_b1, px, C);
    k_head2<<<warpGrid, 256>>>(px, head_w2, head_b2, out);
}

// round 2
// speedup vs baseline: 1.0329x; 1.0329x over previous
#include <cuda_runtime.h>
#include <math.h>

#define N_NODES 50000
#define N_EDGES 500000
#define C 128
#define G3 384
#define NC (N_NODES*C)

// ---------------- scratch (device globals; no allocations allowed) ----------
__device__ float g_h[NC];
__device__ float g_m[NC];
__device__ float g_x[NC];
__device__ float g_agg[NC];
__device__ float g_tot[NC];
__device__ float g_gi[N_NODES*G3];
__device__ float g_gh[N_NODES*G3];

// ---------------- feature build ---------------------------------------------
__global__ void k_feat(const int* __restrict__ xt, const int* __restrict__ xk,
                       const float* __restrict__ xs, float* __restrict__ h) {
    int i = blockIdx.x;
    int c = threadIdx.x;
    int t = xt[i];
    int k = xk[i];
    k = min(max(k, 0), 93);
    float v;
    if (c < 32)       v = (c == t) ? 1.f : 0.f;
    else if (c < 126) v = ((c - 32) == k) ? 1.f : 0.f;
    else              v = xs[i * 2 + (c - 126)];
    h[(size_t)i * C + c] = v;
}

// ---------------- utility ----------------------------------------------------
__global__ void k_zero(float* __restrict__ p, int n4) {
    int i = blockIdx.x * blockDim.x + threadIdx.x;
    if (i < n4) ((float4*)p)[i] = make_float4(0.f, 0.f, 0.f, 0.f);
}

// ---------------- GEMM: Y[128x128 tile] = A[N,128] x op(B) -------------------
// TB=false: Y[i,j] = sum_k A[i,k] * B[k,j]   (B row-major [128,128], col0==0)
// TB=true : Y[i,j] = sum_k A[i,k] * B[j,k]   (B row-major [Ncols,128])
// 256 threads, 8x8 micro-tile per thread, K in chunks of 8 staged in smem,
// register-prefetch pipeline. Inner loop: 4x LDS.128 + 64 FFMA per k.
template<bool TB, bool BIAS, bool RELU>
__global__ void __launch_bounds__(256, 2)
k_gemm2(const float* __restrict__ A, const float* __restrict__ B,
        const float* __restrict__ bias, float* __restrict__ Y, int ystride) {
    __shared__ float As[8][132];
    __shared__ float Bs[8][132];

    const int tid  = threadIdx.x;
    const int row0 = blockIdx.x * 128;
    const int col0 = blockIdx.y * 128;

    // A staging indices: one float4 along k per thread
    const int ar   = tid >> 1;            // 0..127 (row within tile)
    const int akq  = (tid & 1) << 2;      // 0 or 4 (k offset within chunk)
    const int grow = row0 + ar;
    const bool aval = grow < N_NODES;

    // B staging indices
    const int bk  = tid >> 5;             // TB=false: k-row 0..7
    const int bj4 = (tid & 31) << 2;      //           j float4 offset
    const int bj  = tid >> 1;             // TB=true:  col 0..127
    const int bkq = (tid & 1) << 2;       //           k offset 0/4

    const float4 z4 = make_float4(0.f, 0.f, 0.f, 0.f);
    float4 aReg, bReg;

    // prologue: load chunk 0
    aReg = aval ? *(const float4*)(A + (size_t)grow * 128 + akq) : z4;
    if (!TB) bReg = *(const float4*)(B + (size_t)bk * 128 + col0 + bj4);
    else     bReg = *(const float4*)(B + (size_t)(col0 + bj) * 128 + bkq);

    const int ty4 = (tid >> 4) << 2;      // 0,4,...,60
    const int tx4 = (tid & 15) << 2;      // 0,4,...,60

    float acc[8][8];
#pragma unroll
    for (int i = 0; i < 8; i++)
#pragma unroll
        for (int j = 0; j < 8; j++) acc[i][j] = 0.f;

#pragma unroll
    for (int kk = 0; kk < 16; kk++) {
        // stage current chunk
        As[akq + 0][ar] = aReg.x;
        As[akq + 1][ar] = aReg.y;
        As[akq + 2][ar] = aReg.z;
        As[akq + 3][ar] = aReg.w;
        if (!TB) {
            *(float4*)&Bs[bk][bj4] = bReg;
        } else {
            Bs[bkq + 0][bj] = bReg.x;
            Bs[bkq + 1][bj] = bReg.y;
            Bs[bkq + 2][bj] = bReg.z;
            Bs[bkq + 3][bj] = bReg.w;
        }
        __syncthreads();

        // prefetch next chunk into registers
        if (kk < 15) {
            int k0 = (kk + 1) << 3;
            aReg = aval ? *(const float4*)(A + (size_t)grow * 128 + k0 + akq) : z4;
            if (!TB) bReg = *(const float4*)(B + (size_t)(k0 + bk) * 128 + col0 + bj4);
            else     bReg = *(const float4*)(B + (size_t)(col0 + bj) * 128 + k0 + bkq);
        }

#pragma unroll
        for (int k = 0; k < 8; k++) {
            float4 a0 = *(const float4*)&As[k][ty4];
            float4 a1 = *(const float4*)&As[k][ty4 + 64];
            float4 b0 = *(const float4*)&Bs[k][tx4];
            float4 b1 = *(const float4*)&Bs[k][tx4 + 64];
            float av[8] = {a0.x, a0.y, a0.z, a0.w, a1.x, a1.y, a1.z, a1.w};
            float bv[8] = {b0.x, b0.y, b0.z, b0.w, b1.x, b1.y, b1.z, b1.w};
#pragma unroll
            for (int i = 0; i < 8; i++)
#pragma unroll
                for (int j = 0; j < 8; j++) acc[i][j] += av[i] * bv[j];
        }
        __syncthreads();
    }

    // epilogue
    float4 bi0 = z4, bi1 = z4;
    if (BIAS) {
        bi0 = *(const float4*)(bias + col0 + tx4);
        bi1 = *(const float4*)(bias + col0 + 64 + tx4);
    }
#pragma unroll
    for (int ib = 0; ib < 2; ib++) {
#pragma unroll
        for (int i = 0; i < 4; i++) {
            int gr = row0 + ty4 + ib * 64 + i;
            if (gr < N_NODES) {
                float* yr = Y + (size_t)gr * ystride + col0;
#pragma unroll
                for (int jb = 0; jb < 2; jb++) {
                    float4 o;
                    const float* a = acc[ib * 4 + i];
                    float4 bb = jb ? bi1 : bi0;
                    o.x = a[jb * 4 + 0] + bb.x;
                    o.y = a[jb * 4 + 1] + bb.y;
                    o.z = a[jb * 4 + 2] + bb.z;
                    o.w = a[jb * 4 + 3] + bb.w;
                    if (RELU) {
                        o.x = fmaxf(o.x, 0.f); o.y = fmaxf(o.y, 0.f);
                        o.z = fmaxf(o.z, 0.f); o.w = fmaxf(o.w, 0.f);
                    }
                    *(float4*)(yr + jb * 64 + tx4) = o;
                }
            }
        }
    }
}

// ---------------- scatter-add: agg[dst] += x[src] for edges of type t --------
__global__ void k_scatter(const float* __restrict__ x, const int* __restrict__ ei,
                          const int* __restrict__ et, int t, float* __restrict__ agg) {
    int gid = blockIdx.x * blockDim.x + threadIdx.x;
    int e = gid >> 5;
    int lane = gid & 31;
    if (e >= N_EDGES) return;
    if (et[e] != t) return;
    int s = ei[e];
    int d = ei[N_EDGES + e];
    float4 v = ((const float4*)(x + (size_t)s * C))[lane];
    float* dst = agg + (size_t)d * C + lane * 4;
    atomicAdd(dst + 0, v.x);
    atomicAdd(dst + 1, v.y);
    atomicAdd(dst + 2, v.z);
    atomicAdd(dst + 3, v.w);
}

// ---------------- GRU gates (gi/gh already have biases), float4 --------------
// mode: 0 = just update m; 1 = tot += m'; 2 = tot = m' (first accumulate)
__global__ void k_gru(const float* __restrict__ gi, const float* __restrict__ gh,
                      const float* __restrict__ min, float* __restrict__ mout,
                      float* __restrict__ tot, int mode) {
    int idx = blockIdx.x * blockDim.x + threadIdx.x;
    if (idx >= NC / 4) return;
    int row = idx >> 5;
    int q = idx & 31;
    const float4* gir = (const float4*)(gi + (size_t)row * G3);
    const float4* ghr = (const float4*)(gh + (size_t)row * G3);
    float4 ir = gir[q],      hr = ghr[q];
    float4 iz = gir[32 + q], hz = ghr[32 + q];
    float4 in = gir[64 + q], hn = ghr[64 + q];
    float4 mv = ((const float4*)min)[idx];
    float4 o;
#define GRU1(comp) { \
    float r = 1.f / (1.f + __expf(-(ir.comp + hr.comp))); \
    float z = 1.f / (1.f + __expf(-(iz.comp + hz.comp))); \
    float n = tanhf(in.comp + r * hn.comp); \
    o.comp = (1.f - z) * n + z * mv.comp; }
    GRU1(x) GRU1(y) GRU1(z) GRU1(w)
#undef GRU1
    ((float4*)mout)[idx] = o;
    if (mode == 1) {
        float4 tv = ((const float4*)tot)[idx];
        tv.x += o.x; tv.y += o.y; tv.z += o.z; tv.w += o.w;
        ((float4*)tot)[idx] = tv;
    } else if (mode == 2) {
        ((float4*)tot)[idx] = o;
    }
}

// ---------------- LayerNorm(h+tot)*g+b, ReLU (warp per node) -----------------
__global__ void k_ln(float* __restrict__ h, const float* __restrict__ tot,
                     const float* __restrict__ g, const float* __restrict__ b) {
    int i = blockIdx.x * 8 + (threadIdx.x >> 5);
    int lane = threadIdx.x & 31;
    if (i >= N_NODES) return;
    float4 hv = ((float4*)(h + (size_t)i * C))[lane];
    float4 tv = ((const float4*)(tot + (size_t)i * C))[lane];
    float4 v = make_float4(hv.x + tv.x, hv.y + tv.y, hv.z + tv.z, hv.w + tv.w);
    float s  = v.x + v.y + v.z + v.w;
    float ss = v.x * v.x + v.y * v.y + v.z * v.z + v.w * v.w;
#pragma unroll
    for (int off = 16; off; off >>= 1) {
        s  += __shfl_xor_sync(0xffffffffu, s, off);
        ss += __shfl_xor_sync(0xffffffffu, ss, off);
    }
    float mu  = s * (1.f / 128.f);
    float var = ss * (1.f / 128.f) - mu * mu;
    float inv = rsqrtf(var + 1e-5f);
    float4 gg = ((const float4*)g)[lane];
    float4 bb = ((const float4*)b)[lane];
    float4 o;
    o.x = fmaxf((v.x - mu) * inv * gg.x + bb.x, 0.f);
    o.y = fmaxf((v.y - mu) * inv * gg.y + bb.y, 0.f);
    o.z = fmaxf((v.z - mu) * inv * gg.z + bb.z, 0.f);
    o.w = fmaxf((v.w - mu) * inv * gg.w + bb.w, 0.f);
    ((float4*)(h + (size_t)i * C))[lane] = o;
}

// ---------------- head second layer (warp per node) --------------------------
__global__ void k_head2(const float* __restrict__ z, const float* __restrict__ w2,
                        const float* __restrict__ b2, float* __restrict__ out) {
    int i = blockIdx.x * 8 + (threadIdx.x >> 5);
    int lane = threadIdx.x & 31;
    if (i >= N_NODES) return;
    float4 zv = ((const float4*)(z + (size_t)i * C))[lane];
    float4 w0 = ((const float4*)w2)[lane];
    float4 w1 = ((const float4*)(w2 + C))[lane];
    float d0 = zv.x * w0.x + zv.y * w0.y + zv.z * w0.z + zv.w * w0.w;
    float d1 = zv.x * w1.x + zv.y * w1.y + zv.z * w1.z + zv.w * w1.w;
#pragma unroll
    for (int off = 16; off; off >>= 1) {
        d0 += __shfl_xor_sync(0xffffffffu, d0, off);
        d1 += __shfl_xor_sync(0xffffffffu, d1, off);
    }
    if (lane == 0) {
        out[(size_t)i * 2 + 0] = d0 + b2[0];
        out[(size_t)i * 2 + 1] = d1 + b2[1];
    }
}

// ---------------- driver -----------------------------------------------------
extern "C" void kernel_launch(void* const* d_in, const int* in_sizes, int n_in,
                              void* d_out, int out_size) {
    const int*   x_type     = (const int*)d_in[0];
    const int*   x_tok      = (const int*)d_in[1];
    const float* x_small    = (const float*)d_in[2];
    const int*   edge_index = (const int*)d_in[3];
    const int*   edge_type  = (const int*)d_in[4];
    const float* conv_w     = (const float*)d_in[5];   // [2,3,3,128,128]
    const float* gru_wih    = (const float*)d_in[6];   // [2,3,384,128]
    const float* gru_whh    = (const float*)d_in[7];
    const float* gru_bih    = (const float*)d_in[8];   // [2,3,384]
    const float* gru_bhh    = (const float*)d_in[9];
    const float* ln_g       = (const float*)d_in[10];  // [2,128]
    const float* ln_b       = (const float*)d_in[11];
    const float* head_w1    = (const float*)d_in[12];  // [128,128]
    const float* head_b1    = (const float*)d_in[13];
    const float* head_w2    = (const float*)d_in[14];  // [2,128]
    const float* head_b2    = (const float*)d_in[15];
    float* out = (float*)d_out;

    float *ph, *pm, *px, *pagg, *ptot, *pgi, *pgh;
    cudaGetSymbolAddress((void**)&ph,   g_h);
    cudaGetSymbolAddress((void**)&pm,   g_m);
    cudaGetSymbolAddress((void**)&px,   g_x);
    cudaGetSymbolAddress((void**)&pagg, g_agg);
    cudaGetSymbolAddress((void**)&ptot, g_tot);
    cudaGetSymbolAddress((void**)&pgi,  g_gi);
    cudaGetSymbolAddress((void**)&pgh,  g_gh);

    const int rowBlocks = (N_NODES + 127) / 128;    // 391
    const int n4 = NC / 4;
    const int zgrid = (n4 + 255) / 256;
    const int warpGrid = (N_NODES + 7) / 8;

    k_feat<<<N_NODES, 128>>>(x_type, x_tok, x_small, ph);

    for (int b = 0; b < 2; b++) {
        for (int t = 0; t < 3; t++) {
            for (int s = 0; s < 3; s++) {
                const float* hin = (s == 0) ? ph : pm;  // m starts as h

                const float* Wc = conv_w + (size_t)(((b * 3 + t) * 3 + s)) * C * C;
                k_gemm2<false, false, false><<<dim3(rowBlocks, 1), 256>>>(
                    hin, Wc, nullptr, px, C);

                k_zero<<<zgrid, 256>>>(pagg, n4);
                k_scatter<<<(N_EDGES * 32) / 256, 256>>>(px, edge_index, edge_type, t, pagg);

                const float* Wih = gru_wih + (size_t)(b * 3 + t) * G3 * C;
                const float* Bih = gru_bih + (size_t)(b * 3 + t) * G3;
                k_gemm2<true, true, false><<<dim3(rowBlocks, 3), 256>>>(
                    pagg, Wih, Bih, pgi, G3);

                const float* Whh = gru_whh + (size_t)(b * 3 + t) * G3 * C;
                const float* Bhh = gru_bhh + (size_t)(b * 3 + t) * G3;
                k_gemm2<true, true, false><<<dim3(rowBlocks, 3), 256>>>(
                    hin, Whh, Bhh, pgh, G3);

                int mode = (s == 2) ? ((t == 0) ? 2 : 1) : 0;
                k_gru<<<(n4 + 255) / 256, 256>>>(pgi, pgh, hin, pm, ptot, mode);
            }
        }
        k_ln<<<warpGrid, 256>>>(ph, ptot, ln_g + b * C, ln_b + b * C);
    }

    // head: z = relu(h @ w1.T + b1) into g_x, then 2-col projection
    k_gemm2<true, true, true><<<dim3(rowBlocks, 1), 256>>>(
        ph, head_w1, head_b1, px, C);
    k_head2<<<warpGrid, 256>>>(px, head_w2, head_b2, out);
}

// round 4
// speedup vs baseline: 1.6555x; 1.6028x over previous
#include <cuda_runtime.h>
#include <cuda_bf16.h>
#include <math.h>
#include <stdint.h>

#define N_NODES 50000
#define N_EDGES 500000
#define C 128
#define G3 384
#define NC (N_NODES*C)

// ---------------- scratch (device globals; no allocations allowed) ----------
__device__ float g_h[NC];
__device__ float g_m[NC];
__device__ float g_x[NC];
__device__ float g_agg[NC];
__device__ float g_tot[NC];
__device__ float g_gi[N_NODES*G3];
__device__ float g_gh[N_NODES*G3];

// ---------------- helpers ----------------------------------------------------
__device__ __forceinline__ uint32_t smem_u32(const void* p) {
    uint32_t a;
    asm("{ .reg .u64 t; cvta.to.shared.u64 t, %1; cvt.u32.u64 %0, t; }"
        : "=r"(a) : "l"(p));
    return a;
}

#define LDSM4(r, addr) \
    asm volatile("ldmatrix.sync.aligned.m8n8.x4.shared.b16 {%0,%1,%2,%3}, [%4];" \
        : "=r"((r)[0]), "=r"((r)[1]), "=r"((r)[2]), "=r"((r)[3]) : "r"(addr))

#define MMA(d, a, b) \
    asm volatile("mma.sync.aligned.m16n8k16.row.col.f32.bf16.bf16.f32 " \
        "{%0,%1,%2,%3}, {%4,%5,%6,%7}, {%8,%9}, {%0,%1,%2,%3};" \
        : "+f"((d)[0]), "+f"((d)[1]), "+f"((d)[2]), "+f"((d)[3]) \
        : "r"((a)[0]), "r"((a)[1]), "r"((a)[2]), "r"((a)[3]), \
          "r"((b)[0]), "r"((b)[1]))

// hi/lo bf16 split of 8 floats -> ushort arrays
__device__ __forceinline__ void cvt8s(const float* v, unsigned short* hs,
                                      unsigned short* ls) {
#pragma unroll
    for (int j = 0; j < 8; j++) {
        __nv_bfloat16 h = __float2bfloat16(v[j]);
        float r = v[j] - __bfloat162float(h);
        __nv_bfloat16 l = __float2bfloat16(r);
        hs[j] = __bfloat16_as_ushort(h);
        ls[j] = __bfloat16_as_ushort(l);
    }
}

// ---------------- tensor-core GEMM (mma.sync bf16, 3-term split) --------------
// Y[i, gc] = sum_k A[i,k] * op(W)[k, gc] (+bias, relu)
// TB=true : op(W)[k,gc] = W[gc*128 + k]     (W row-major [Ncols,128])
// TB=false: op(W)[k,gc] = W[k*128 + gc]     (W row-major [128,128], NB==1)
// Grid: (ceil(N/128), NB). Y row stride = NB*128. col block = blockIdx.y.
// SMEM: Ah/Al/Bh/Bl, each 128 rows x 136 bf16 (pad => conflict-free ldmatrix).
#define TS 136                     // row stride in bf16 elems
#define MAT_BYTES (128 * TS * 2)   // 34816
template<bool TB, bool BIAS, bool RELU, int NB>
__global__ void __launch_bounds__(256, 1)
k_mma(const float* __restrict__ A, const float* __restrict__ W,
      const float* __restrict__ bias, float* __restrict__ Y) {
    constexpr int YS = NB * 128;
    extern __shared__ char sm[];
    __nv_bfloat16* AH = (__nv_bfloat16*)(sm);
    __nv_bfloat16* AL = (__nv_bfloat16*)(sm + MAT_BYTES);
    __nv_bfloat16* BH = (__nv_bfloat16*)(sm + 2 * MAT_BYTES);
    __nv_bfloat16* BL = (__nv_bfloat16*)(sm + 3 * MAT_BYTES);

    const int tid  = threadIdx.x;
    const int row0 = blockIdx.x * 128;
    const int col0 = blockIdx.y * 128;

    // ---- stage A (hi/lo), 2048 granules of 8 elems ----
#pragma unroll
    for (int i = 0; i < 8; i++) {
        int g = tid + i * 256;
        int r = g >> 4, k8 = (g & 15) * 8;
        float v[8];
        if (row0 + r < N_NODES) {
            const float4* p = (const float4*)(A + (size_t)(row0 + r) * 128 + k8);
            float4 q0 = p[0], q1 = p[1];
            v[0]=q0.x; v[1]=q0.y; v[2]=q0.z; v[3]=q0.w;
            v[4]=q1.x; v[5]=q1.y; v[6]=q1.z; v[7]=q1.w;
        } else {
#pragma unroll
            for (int j = 0; j < 8; j++) v[j] = 0.f;
        }
        unsigned short hs[8], ls[8];
        cvt8s(v, hs, ls);
        int off = r * TS + k8;
#pragma unroll
        for (int j = 0; j < 8; j++) {
            AH[off + j] = __ushort_as_bfloat16(hs[j]);
            AL[off + j] = __ushort_as_bfloat16(ls[j]);
        }
    }

    // ---- stage B (hi/lo) as [n][k] ----
#pragma unroll
    for (int i = 0; i < 8; i++) {
        int g = tid + i * 256;
        unsigned short hs[8], ls[8];
        if (TB) {
            int n = g >> 4, k8 = (g & 15) * 8;
            const float4* p = (const float4*)(W + (size_t)(col0 + n) * 128 + k8);
            float4 q0 = p[0], q1 = p[1];
            float v[8] = {q0.x,q0.y,q0.z,q0.w,q1.x,q1.y,q1.z,q1.w};
            cvt8s(v, hs, ls);
            int off = n * TS + k8;
#pragma unroll
            for (int j = 0; j < 8; j++) {
                BH[off + j] = __ushort_as_bfloat16(hs[j]);
                BL[off + j] = __ushort_as_bfloat16(ls[j]);
            }
        } else {
            // W row-major [k][n]; load coalesced along n, scatter-transpose to [n][k]
            int kk = g >> 4, n8 = (g & 15) * 8;
            const float4* p = (const float4*)(W + (size_t)kk * 128 + n8);
            float4 q0 = p[0], q1 = p[1];
            float v[8] = {q0.x,q0.y,q0.z,q0.w,q1.x,q1.y,q1.z,q1.w};
            cvt8s(v, hs, ls);
#pragma unroll
            for (int j = 0; j < 8; j++) {
                BH[(n8 + j) * TS + kk] = __ushort_as_bfloat16(hs[j]);
                BL[(n8 + j) * TS + kk] = __ushort_as_bfloat16(ls[j]);
            }
        }
    }
    __syncthreads();

    // ---- compute: 8 warps, warp tile 32(m) x 64(n) ----
    const int wid  = tid >> 5, lane = tid & 31;
    const int m0 = (wid & 3) * 32;
    const int n0 = (wid >> 2) * 64;
    const int arow = lane & 15;
    const int acol = (lane >> 4) << 3;
    const int brow = (lane & 7) + ((lane >> 4) << 3);
    const int bcol = ((lane >> 3) & 1) << 3;

    const uint32_t uAH = smem_u32(AH), uAL = smem_u32(AL);
    const uint32_t uBH = smem_u32(BH), uBL = smem_u32(BL);

    float acc[2][8][4];
#pragma unroll
    for (int mi = 0; mi < 2; mi++)
#pragma unroll
        for (int nj = 0; nj < 8; nj++)
#pragma unroll
            for (int q = 0; q < 4; q++) acc[mi][nj][q] = 0.f;

#pragma unroll
    for (int ks = 0; ks < 8; ks++) {
        const int k = ks * 16;
        uint32_t ah[2][4], al[2][4];
#pragma unroll
        for (int mi = 0; mi < 2; mi++) {
            uint32_t off = (uint32_t)(((m0 + mi * 16 + arow) * TS + k + acol) * 2);
            LDSM4(ah[mi], uAH + off);
            LDSM4(al[mi], uAL + off);
        }
        uint32_t bh[8][2], bl[8][2];
#pragma unroll
        for (int nq = 0; nq < 4; nq++) {
            uint32_t off = (uint32_t)(((n0 + nq * 16 + brow) * TS + k + bcol) * 2);
            uint32_t r4[4];
            LDSM4(r4, uBH + off);
            bh[2*nq][0]=r4[0]; bh[2*nq][1]=r4[1]; bh[2*nq+1][0]=r4[2]; bh[2*nq+1][1]=r4[3];
            LDSM4(r4, uBL + off);
            bl[2*nq][0]=r4[0]; bl[2*nq][1]=r4[1]; bl[2*nq+1][0]=r4[2]; bl[2*nq+1][1]=r4[3];
        }
#pragma unroll
        for (int mi = 0; mi < 2; mi++)
#pragma unroll
            for (int nj = 0; nj < 8; nj++) {
                MMA(acc[mi][nj], ah[mi], bh[nj]);
                MMA(acc[mi][nj], ah[mi], bl[nj]);
                MMA(acc[mi][nj], al[mi], bh[nj]);
            }
    }

    // ---- epilogue ----
    const int rbase = row0 + m0 + (lane >> 2);
    const int cbase = n0 + (lane & 3) * 2;
#pragma unroll
    for (int mi = 0; mi < 2; mi++) {
#pragma unroll
        for (int nj = 0; nj < 8; nj++) {
            int gr = rbase + mi * 16;
            int gc = col0 + cbase + nj * 8;
            float b0 = 0.f, b1 = 0.f;
            if (BIAS) { b0 = bias[gc]; b1 = bias[gc + 1]; }
            float2 v0, v1;
            v0.x = acc[mi][nj][0] + b0; v0.y = acc[mi][nj][1] + b1;
            v1.x = acc[mi][nj][2] + b0; v1.y = acc[mi][nj][3] + b1;
            if (RELU) {
                v0.x = fmaxf(v0.x, 0.f); v0.y = fmaxf(v0.y, 0.f);
                v1.x = fmaxf(v1.x, 0.f); v1.y = fmaxf(v1.y, 0.f);
            }
            if (gr < N_NODES)
                *(float2*)(Y + (size_t)gr * YS + gc) = v0;
            if (gr + 8 < N_NODES)
                *(float2*)(Y + (size_t)(gr + 8) * YS + gc) = v1;
        }
    }
}

// ---------------- feature build ---------------------------------------------
__global__ void k_feat(const int* __restrict__ xt, const int* __restrict__ xk,
                       const float* __restrict__ xs, float* __restrict__ h) {
    int i = blockIdx.x;
    int c = threadIdx.x;
    int t = xt[i];
    int k = xk[i];
    k = min(max(k, 0), 93);
    float v;
    if (c < 32)       v = (c == t) ? 1.f : 0.f;
    else if (c < 126) v = ((c - 32) == k) ? 1.f : 0.f;
    else              v = xs[i * 2 + (c - 126)];
    h[(size_t)i * C + c] = v;
}

__global__ void k_zero(float* __restrict__ p, int n4) {
    int i = blockIdx.x * blockDim.x + threadIdx.x;
    if (i < n4) ((float4*)p)[i] = make_float4(0.f, 0.f, 0.f, 0.f);
}

// ---------------- scatter-add: agg[dst] += x[src] for edges of type t --------
__global__ void k_scatter(const float* __restrict__ x, const int* __restrict__ ei,
                          const int* __restrict__ et, int t, float* __restrict__ agg) {
    int gid = blockIdx.x * blockDim.x + threadIdx.x;
    int e = gid >> 5;
    int lane = gid & 31;
    if (e >= N_EDGES) return;
    if (et[e] != t) return;
    int s = ei[e];
    int d = ei[N_EDGES + e];
    float4 v = ((const float4*)(x + (size_t)s * C))[lane];
    float* dst = agg + (size_t)d * C + lane * 4;
    atomicAdd(dst + 0, v.x);
    atomicAdd(dst + 1, v.y);
    atomicAdd(dst + 2, v.z);
    atomicAdd(dst + 3, v.w);
}

// ---------------- GRU gates + agg re-zero ------------------------------------
// mode: 0 = update m only; 1 = tot += m'; 2 = tot = m'
__global__ void k_gru(const float* __restrict__ gi, const float* __restrict__ gh,
                      const float* __restrict__ min, float* __restrict__ mout,
                      float* __restrict__ tot, int mode, float* __restrict__ aggz) {
    int idx = blockIdx.x * blockDim.x + threadIdx.x;
    if (idx >= NC / 4) return;
    int row = idx >> 5;
    int q = idx & 31;
    const float4* gir = (const float4*)(gi + (size_t)row * G3);
    const float4* ghr = (const float4*)(gh + (size_t)row * G3);
    float4 ir = gir[q],      hr = ghr[q];
    float4 iz = gir[32 + q], hz = ghr[32 + q];
    float4 in = gir[64 + q], hn = ghr[64 + q];
    float4 mv = ((const float4*)min)[idx];
    float4 o;
#define GRU1(comp) { \
    float r = 1.f / (1.f + __expf(-(ir.comp + hr.comp))); \
    float z = 1.f / (1.f + __expf(-(iz.comp + hz.comp))); \
    float n = tanhf(in.comp + r * hn.comp); \
    o.comp = (1.f - z) * n + z * mv.comp; }
    GRU1(x) GRU1(y) GRU1(z) GRU1(w)
#undef GRU1
    ((float4*)mout)[idx] = o;
    ((float4*)aggz)[idx] = make_float4(0.f, 0.f, 0.f, 0.f);  // pre-zero next scatter
    if (mode == 1) {
        float4 tv = ((const float4*)tot)[idx];
        tv.x += o.x; tv.y += o.y; tv.z += o.z; tv.w += o.w;
        ((float4*)tot)[idx] = tv;
    } else if (mode == 2) {
        ((float4*)tot)[idx] = o;
    }
}

// ---------------- LayerNorm(h+tot)*g+b, ReLU (warp per node) -----------------
__global__ void k_ln(float* __restrict__ h, const float* __restrict__ tot,
                     const float* __restrict__ g, const float* __restrict__ b) {
    int i = blockIdx.x * 8 + (threadIdx.x >> 5);
    int lane = threadIdx.x & 31;
    if (i >= N_NODES) return;
    float4 hv = ((float4*)(h + (size_t)i * C))[lane];
    float4 tv = ((const float4*)(tot + (size_t)i * C))[lane];
    float4 v = make_float4(hv.x + tv.x, hv.y + tv.y, hv.z + tv.z, hv.w + tv.w);
    float s  = v.x + v.y + v.z + v.w;
    float ss = v.x * v.x + v.y * v.y + v.z * v.z + v.w * v.w;
#pragma unroll
    for (int off = 16; off; off >>= 1) {
        s  += __shfl_xor_sync(0xffffffffu, s, off);
        ss += __shfl_xor_sync(0xffffffffu, ss, off);
    }
    float mu  = s * (1.f / 128.f);
    float var = ss * (1.f / 128.f) - mu * mu;
    float inv = rsqrtf(var + 1e-5f);
    float4 gg = ((const float4*)g)[lane];
    float4 bb = ((const float4*)b)[lane];
    float4 o;
    o.x = fmaxf((v.x - mu) * inv * gg.x + bb.x, 0.f);
    o.y = fmaxf((v.y - mu) * inv * gg.y + bb.y, 0.f);
    o.z = fmaxf((v.z - mu) * inv * gg.z + bb.z, 0.f);
    o.w = fmaxf((v.w - mu) * inv * gg.w + bb.w, 0.f);
    ((float4*)(h + (size_t)i * C))[lane] = o;
}

// ---------------- head second layer (warp per node) --------------------------
__global__ void k_head2(const float* __restrict__ z, const float* __restrict__ w2,
                        const float* __restrict__ b2, float* __restrict__ out) {
    int i = blockIdx.x * 8 + (threadIdx.x >> 5);
    int lane = threadIdx.x & 31;
    if (i >= N_NODES) return;
    float4 zv = ((const float4*)(z + (size_t)i * C))[lane];
    float4 w0 = ((const float4*)w2)[lane];
    float4 w1 = ((const float4*)(w2 + C))[lane];
    float d0 = zv.x * w0.x + zv.y * w0.y + zv.z * w0.z + zv.w * w0.w;
    float d1 = zv.x * w1.x + zv.y * w1.y + zv.z * w1.z + zv.w * w1.w;
#pragma unroll
    for (int off = 16; off; off >>= 1) {
        d0 += __shfl_xor_sync(0xffffffffu, d0, off);
        d1 += __shfl_xor_sync(0xffffffffu, d1, off);
    }
    if (lane == 0) {
        out[(size_t)i * 2 + 0] = d0 + b2[0];
        out[(size_t)i * 2 + 1] = d1 + b2[1];
    }
}

// ---------------- driver -----------------------------------------------------
extern "C" void kernel_launch(void* const* d_in, const int* in_sizes, int n_in,
                              void* d_out, int out_size) {
    const int*   x_type     = (const int*)d_in[0];
    const int*   x_tok      = (const int*)d_in[1];
    const float* x_small    = (const float*)d_in[2];
    const int*   edge_index = (const int*)d_in[3];
    const int*   edge_type  = (const int*)d_in[4];
    const float* conv_w     = (const float*)d_in[5];   // [2,3,3,128,128]
    const float* gru_wih    = (const float*)d_in[6];   // [2,3,384,128]
    const float* gru_whh    = (const float*)d_in[7];
    const float* gru_bih    = (const float*)d_in[8];   // [2,3,384]
    const float* gru_bhh    = (const float*)d_in[9];
    const float* ln_g       = (const float*)d_in[10];  // [2,128]
    const float* ln_b       = (const float*)d_in[11];
    const float* head_w1    = (const float*)d_in[12];  // [128,128]
    const float* head_b1    = (const float*)d_in[13];
    const float* head_w2    = (const float*)d_in[14];  // [2,128]
    const float* head_b2    = (const float*)d_in[15];
    float* out = (float*)d_out;

    float *ph, *pm, *px, *pagg, *ptot, *pgi, *pgh;
    cudaGetSymbolAddress((void**)&ph,   g_h);
    cudaGetSymbolAddress((void**)&pm,   g_m);
    cudaGetSymbolAddress((void**)&px,   g_x);
    cudaGetSymbolAddress((void**)&pagg, g_agg);
    cudaGetSymbolAddress((void**)&ptot, g_tot);
    cudaGetSymbolAddress((void**)&pgi,  g_gi);
    cudaGetSymbolAddress((void**)&pgh,  g_gh);

    const int SMEMSZ = 4 * MAT_BYTES;   // 139264
    cudaFuncSetAttribute(k_mma<false, false, false, 1>,
                         cudaFuncAttributeMaxDynamicSharedMemorySize, SMEMSZ);
    cudaFuncSetAttribute(k_mma<true, true, false, 3>,
                         cudaFuncAttributeMaxDynamicSharedMemorySize, SMEMSZ);
    cudaFuncSetAttribute(k_mma<true, true, true, 1>,
                         cudaFuncAttributeMaxDynamicSharedMemorySize, SMEMSZ);

    const int rowBlocks = (N_NODES + 127) / 128;    // 391
    const int n4 = NC / 4;
    const int zgrid = (n4 + 255) / 256;
    const int warpGrid = (N_NODES + 7) / 8;

    k_feat<<<N_NODES, 128>>>(x_type, x_tok, x_small, ph);
    k_zero<<<zgrid, 256>>>(pagg, n4);   // initial agg zero (k_gru re-zeros after)

    for (int b = 0; b < 2; b++) {
        for (int t = 0; t < 3; t++) {
            for (int s = 0; s < 3; s++) {
                const float* hin = (s == 0) ? ph : pm;  // m starts as h

                const float* Wc = conv_w + (size_t)(((b * 3 + t) * 3 + s)) * C * C;
                k_mma<false, false, false, 1><<<dim3(rowBlocks, 1), 256, SMEMSZ>>>(
                    hin, Wc, nullptr, px);

                k_scatter<<<(N_EDGES * 32) / 256, 256>>>(px, edge_index, edge_type, t, pagg);

                const float* Wih = gru_wih + (size_t)(b * 3 + t) * G3 * C;
                const float* Bih = gru_bih + (size_t)(b * 3 + t) * G3;
                k_mma<true, true, false, 3><<<dim3(rowBlocks, 3), 256, SMEMSZ>>>(
                    pagg, Wih, Bih, pgi);

                const float* Whh = gru_whh + (size_t)(b * 3 + t) * G3 * C;
                const float* Bhh = gru_bhh + (size_t)(b * 3 + t) * G3;
                k_mma<true, true, false, 3><<<dim3(rowBlocks, 3), 256, SMEMSZ>>>(
                    hin, Whh, Bhh, pgh);

                int mode = (s == 2) ? ((t == 0) ? 2 : 1) : 0;
                k_gru<<<(n4 + 255) / 256, 256>>>(pgi, pgh, hin, pm, ptot, mode, pagg);
            }
        }
        k_ln<<<warpGrid, 256>>>(ph, ptot, ln_g + b * C, ln_b + b * C);
    }

    // head: z = relu(h @ w1.T + b1) into g_x, then 2-col projection
    k_mma<true, true, true, 1><<<dim3(rowBlocks, 1), 256, SMEMSZ>>>(
        ph, head_w1, head_b1, px);
    k_head2<<<warpGrid, 256>>>(px, head_w2, head_b2, out);
}

// round 5
// speedup vs baseline: 2.3059x; 1.3929x over previous
#include <cuda_runtime.h>
#include <cuda_bf16.h>
#include <math.h>
#include <stdint.h>

#define N_NODES 50000
#define N_EDGES 500000
#define C 128
#define G3 384
#define NC (N_NODES*C)
#define M3 (3*N_NODES)

typedef __nv_bfloat16 bf16;
typedef __nv_bfloat162 bf162;

// ---------------- scratch (device globals) -----------------------------------
__device__ float g_h[NC];
__device__ float g_m[NC];
__device__ float g_x[NC];
__device__ float g_tot[NC];
__device__ float g_gi[N_NODES*G3];
__device__ float g_gh[N_NODES*G3];
__device__ bf16  g_hh[NC], g_hl[NC];
__device__ bf16  g_mh[NC], g_ml[NC];
__device__ bf16  g_ah[NC], g_al[NC];
// weights (bf16 hi/lo, B as [n][k])
__device__ bf16  g_wch[18*C*C], g_wcl[18*C*C];
__device__ bf16  g_wihh[6*G3*C], g_wihl[6*G3*C];
__device__ bf16  g_whhh[6*G3*C], g_whhl[6*G3*C];
__device__ bf16  g_w1h[C*C], g_w1l[C*C];
// CSR
__device__ int g_cnt[M3], g_incl[M3], g_cur[M3], g_bsum[256];
__device__ int g_indptr[M3+1];
__device__ int g_eidx[N_EDGES];

// ---------------- helpers ----------------------------------------------------
__device__ __forceinline__ uint32_t smem_u32(const void* p) {
    uint32_t a;
    asm("{ .reg .u64 t; cvta.to.shared.u64 t, %1; cvt.u32.u64 %0, t; }"
        : "=r"(a) : "l"(p));
    return a;
}

#define LDSM4(r, addr) \
    asm volatile("ldmatrix.sync.aligned.m8n8.x4.shared.b16 {%0,%1,%2,%3}, [%4];" \
        : "=r"((r)[0]), "=r"((r)[1]), "=r"((r)[2]), "=r"((r)[3]) : "r"(addr))

#define MMA(d, a, b) \
    asm volatile("mma.sync.aligned.m16n8k16.row.col.f32.bf16.bf16.f32 " \
        "{%0,%1,%2,%3}, {%4,%5,%6,%7}, {%8,%9}, {%0,%1,%2,%3};" \
        : "+f"((d)[0]), "+f"((d)[1]), "+f"((d)[2]), "+f"((d)[3]) \
        : "r"((a)[0]), "r"((a)[1]), "r"((a)[2]), "r"((a)[3]), \
          "r"((b)[0]), "r"((b)[1]))

__device__ __forceinline__ void split1(float v, bf16& h, bf16& l) {
    h = __float2bfloat16(v);
    l = __float2bfloat16(v - __bfloat162float(h));
}

// ---------------- weight conversion ------------------------------------------
__global__ void k_cvtpair(const float* __restrict__ in, bf16* __restrict__ oh,
                          bf16* __restrict__ ol, int n) {
    int i = blockIdx.x * 256 + threadIdx.x;
    if (i >= n) return;
    bf16 h, l; split1(in[i], h, l);
    oh[i] = h; ol[i] = l;
}

// conv_w [18][k][n] -> [18][n][k] hi/lo
__global__ void k_cvt_tr(const float* __restrict__ in, bf16* __restrict__ oh,
                         bf16* __restrict__ ol) {
    int idx = blockIdx.x * 256 + threadIdx.x;
    if (idx >= 18 * C * C) return;
    int w = idx >> 14, rem = idx & 16383;
    int nn = rem >> 7, kk = rem & 127;
    float v = in[(w << 14) + (kk << 7) + nn];
    bf16 h, l; split1(v, h, l);
    oh[idx] = h; ol[idx] = l;
}

// ---------------- CSR build --------------------------------------------------
__global__ void k_izero(int* __restrict__ p, int n) {
    int i = blockIdx.x * 256 + threadIdx.x;
    if (i < n) p[i] = 0;
}
__global__ void k_count(const int* __restrict__ ei, const int* __restrict__ et,
                        int* __restrict__ cnt) {
    int e = blockIdx.x * 256 + threadIdx.x;
    if (e >= N_EDGES) return;
    atomicAdd(cnt + et[e] * N_NODES + ei[N_EDGES + e], 1);
}
__global__ void k_scan1(const int* __restrict__ cnt, int* __restrict__ incl,
                        int* __restrict__ bsum) {
    __shared__ int sm[1024];
    int i = blockIdx.x * 1024 + threadIdx.x;
    int v = (i < M3) ? cnt[i] : 0;
    sm[threadIdx.x] = v;
    __syncthreads();
#pragma unroll
    for (int off = 1; off < 1024; off <<= 1) {
        int t = (threadIdx.x >= off) ? sm[threadIdx.x - off] : 0;
        __syncthreads();
        sm[threadIdx.x] += t;
        __syncthreads();
    }
    if (i < M3) incl[i] = sm[threadIdx.x];
    if (threadIdx.x == 1023) bsum[blockIdx.x] = sm[1023];
}
__global__ void k_scan2(int* __restrict__ bsum, int nb) {
    if (blockIdx.x == 0 && threadIdx.x == 0) {
        int acc = 0;
        for (int b = 0; b < nb; b++) { int v = bsum[b]; bsum[b] = acc; acc += v; }
    }
}
__global__ void k_scan3(const int* __restrict__ incl, const int* __restrict__ bsum,
                        int* __restrict__ indptr, int* __restrict__ cur) {
    int i = blockIdx.x * 1024 + threadIdx.x;
    if (i < M3) {
        int v = incl[i] + bsum[blockIdx.x];
        indptr[i + 1] = v;
        cur[i] = v - ((i < M3) ? 0 : 0);  // placeholder; cur fixed below
    }
    if (i == 0) indptr[0] = 0;
}
__global__ void k_curinit(const int* __restrict__ indptr, int* __restrict__ cur) {
    int i = blockIdx.x * 256 + threadIdx.x;
    if (i < M3) cur[i] = indptr[i];
}
__global__ void k_fill(const int* __restrict__ ei, const int* __restrict__ et,
                       int* __restrict__ cur, int* __restrict__ eidx) {
    int e = blockIdx.x * 256 + threadIdx.x;
    if (e >= N_EDGES) return;
    int tn = et[e] * N_NODES + ei[N_EDGES + e];
    int p = atomicAdd(cur + tn, 1);
    eidx[p] = ei[e];
}

// ---------------- gather: agg[dst] = sum x[src], bf16 hi/lo out --------------
__global__ void k_gather(const float* __restrict__ x, const int* __restrict__ eidx,
                         const int* __restrict__ indptr, int t,
                         bf16* __restrict__ aggh, bf16* __restrict__ aggl) {
    int w = blockIdx.x * 8 + (threadIdx.x >> 5);
    int lane = threadIdx.x & 31;
    if (w >= N_NODES) return;
    int tn = t * N_NODES + w;
    int beg = indptr[tn], end = indptr[tn + 1];
    float4 s = make_float4(0.f, 0.f, 0.f, 0.f);
    for (int j = beg; j < end; j++) {
        int src = eidx[j];
        float4 v = ((const float4*)x)[src * 32 + lane];
        s.x += v.x; s.y += v.y; s.z += v.z; s.w += v.w;
    }
    bf16 hx, lx, hy, ly, hz, lz, hw, lw;
    split1(s.x, hx, lx); split1(s.y, hy, ly);
    split1(s.z, hz, lz); split1(s.w, hw, lw);
    bf162 h01; h01.x = hx; h01.y = hy;
    bf162 h23; h23.x = hz; h23.y = hw;
    bf162 l01; l01.x = lx; l01.y = ly;
    bf162 l23; l23.x = lz; l23.y = lw;
    size_t o = (size_t)w * C + lane * 4;
    *(bf162*)(aggh + o)     = h01;
    *(bf162*)(aggh + o + 2) = h23;
    *(bf162*)(aggl + o)     = l01;
    *(bf162*)(aggl + o + 2) = l23;
}

// ---------------- tensor-core GEMM (pre-split bf16 operands) ------------------
// Y[i, blk*128+c] = sum_k A[i,k] * W[blk*128+c, k]  (+bias, relu)
// A hi/lo: [N,128] bf16. W hi/lo: [NB*128][128] bf16 (n-major). Y stride NB*128.
#define TS 136
#define MAT_BYTES (128 * TS * 2)   // 34816
template<bool BIAS, bool RELU, int NB>
__global__ void __launch_bounds__(256, 1)
k_mma2(const bf16* __restrict__ Ah, const bf16* __restrict__ Al,
       const bf16* __restrict__ Wh, const bf16* __restrict__ Wl,
       const float* __restrict__ bias, float* __restrict__ Y) {
    constexpr int YS = NB * 128;
    extern __shared__ char sm[];
    bf16* AH = (bf16*)(sm);
    bf16* AL = (bf16*)(sm + MAT_BYTES);
    bf16* BH = (bf16*)(sm + 2 * MAT_BYTES);
    bf16* BL = (bf16*)(sm + 3 * MAT_BYTES);

    const int tid  = threadIdx.x;
    const int row0 = blockIdx.x * 128;

    // ---- stage A hi/lo (vectorized) ----
#pragma unroll
    for (int i = 0; i < 8; i++) {
        int g = tid + i * 256;
        int r = g >> 4, k8 = (g & 15) * 8;
        uint4 vh = make_uint4(0u, 0u, 0u, 0u), vl = vh;
        if (row0 + r < N_NODES) {
            vh = *(const uint4*)(Ah + (size_t)(row0 + r) * C + k8);
            vl = *(const uint4*)(Al + (size_t)(row0 + r) * C + k8);
        }
        *(uint4*)(AH + r * TS + k8) = vh;
        *(uint4*)(AL + r * TS + k8) = vl;
    }

    const int wid  = tid >> 5, lane = tid & 31;
    const int m0 = (wid & 3) * 32;
    const int n0 = (wid >> 2) * 64;
    const int arow = lane & 15;
    const int acol = (lane >> 4) << 3;
    const int brow = (lane & 7) + ((lane >> 4) << 3);
    const int bcol = ((lane >> 3) & 1) << 3;
    const uint32_t uAH = smem_u32(AH), uAL = smem_u32(AL);
    const uint32_t uBH = smem_u32(BH), uBL = smem_u32(BL);

    const int rbase = row0 + m0 + (lane >> 2);
    const int cbase = n0 + (lane & 3) * 2;

#pragma unroll
    for (int blk = 0; blk < NB; blk++) {
        __syncthreads();   // A visible (blk0); Bs free of prior readers (blk>0)
        // ---- stage B block hi/lo ----
#pragma unroll
        for (int i = 0; i < 8; i++) {
            int g = tid + i * 256;
            int n = g >> 4, k8 = (g & 15) * 8;
            *(uint4*)(BH + n * TS + k8) =
                *(const uint4*)(Wh + (size_t)(blk * 128 + n) * C + k8);
            *(uint4*)(BL + n * TS + k8) =
                *(const uint4*)(Wl + (size_t)(blk * 128 + n) * C + k8);
        }
        __syncthreads();

        float acc[2][8][4];
#pragma unroll
        for (int mi = 0; mi < 2; mi++)
#pragma unroll
            for (int nj = 0; nj < 8; nj++)
#pragma unroll
                for (int q = 0; q < 4; q++) acc[mi][nj][q] = 0.f;

#pragma unroll
        for (int ks = 0; ks < 8; ks++) {
            const int k = ks * 16;
            uint32_t ah[2][4], al[2][4];
#pragma unroll
            for (int mi = 0; mi < 2; mi++) {
                uint32_t off = (uint32_t)(((m0 + mi * 16 + arow) * TS + k + acol) * 2);
                LDSM4(ah[mi], uAH + off);
                LDSM4(al[mi], uAL + off);
            }
            uint32_t bh[8][2], bl[8][2];
#pragma unroll
            for (int nq = 0; nq < 4; nq++) {
                uint32_t off = (uint32_t)(((n0 + nq * 16 + brow) * TS + k + bcol) * 2);
                uint32_t r4[4];
                LDSM4(r4, uBH + off);
                bh[2*nq][0]=r4[0]; bh[2*nq][1]=r4[1]; bh[2*nq+1][0]=r4[2]; bh[2*nq+1][1]=r4[3];
                LDSM4(r4, uBL + off);
                bl[2*nq][0]=r4[0]; bl[2*nq][1]=r4[1]; bl[2*nq+1][0]=r4[2]; bl[2*nq+1][1]=r4[3];
            }
#pragma unroll
            for (int mi = 0; mi < 2; mi++)
#pragma unroll
                for (int nj = 0; nj < 8; nj++) {
                    MMA(acc[mi][nj], ah[mi], bh[nj]);
                    MMA(acc[mi][nj], ah[mi], bl[nj]);
                    MMA(acc[mi][nj], al[mi], bh[nj]);
                }
        }

        // ---- epilogue for this block ----
#pragma unroll
        for (int mi = 0; mi < 2; mi++) {
#pragma unroll
            for (int nj = 0; nj < 8; nj++) {
                int gr = rbase + mi * 16;
                int gc = blk * 128 + cbase + nj * 8;
                float b0 = 0.f, b1 = 0.f;
                if (BIAS) { b0 = bias[gc]; b1 = bias[gc + 1]; }
                float2 v0, v1;
                v0.x = acc[mi][nj][0] + b0; v0.y = acc[mi][nj][1] + b1;
                v1.x = acc[mi][nj][2] + b0; v1.y = acc[mi][nj][3] + b1;
                if (RELU) {
                    v0.x = fmaxf(v0.x, 0.f); v0.y = fmaxf(v0.y, 0.f);
                    v1.x = fmaxf(v1.x, 0.f); v1.y = fmaxf(v1.y, 0.f);
                }
                if (gr < N_NODES)
                    *(float2*)(Y + (size_t)gr * YS + gc) = v0;
                if (gr + 8 < N_NODES)
                    *(float2*)(Y + (size_t)(gr + 8) * YS + gc) = v1;
            }
        }
    }
}

// ---------------- feature build (fp32 + bf16 hi/lo) --------------------------
__global__ void k_feat(const int* __restrict__ xt, const int* __restrict__ xk,
                       const float* __restrict__ xs, float* __restrict__ h,
                       bf16* __restrict__ hh, bf16* __restrict__ hl) {
    int i = blockIdx.x;
    int c = threadIdx.x;
    int t = xt[i];
    int k = xk[i];
    k = min(max(k, 0), 93);
    float v;
    if (c < 32)       v = (c == t) ? 1.f : 0.f;
    else if (c < 126) v = ((c - 32) == k) ? 1.f : 0.f;
    else              v = xs[i * 2 + (c - 126)];
    size_t o = (size_t)i * C + c;
    h[o] = v;
    bf16 bh, bl; split1(v, bh, bl);
    hh[o] = bh; hl[o] = bl;
}

// ---------------- GRU gates (+ bf16 split of m') -----------------------------
// mode: 0 = update m only; 1 = tot += m'; 2 = tot = m'
__global__ void k_gru(const float* __restrict__ gi, const float* __restrict__ gh,
                      const float* __restrict__ min, float* __restrict__ mout,
                      bf16* __restrict__ mh, bf16* __restrict__ ml,
                      float* __restrict__ tot, int mode) {
    int idx = blockIdx.x * blockDim.x + threadIdx.x;
    if (idx >= NC / 4) return;
    int row = idx >> 5;
    int q = idx & 31;
    const float4* gir = (const float4*)(gi + (size_t)row * G3);
    const float4* ghr = (const float4*)(gh + (size_t)row * G3);
    float4 ir = gir[q],      hr = ghr[q];
    float4 iz = gir[32 + q], hz = ghr[32 + q];
    float4 in = gir[64 + q], hn = ghr[64 + q];
    float4 mv = ((const float4*)min)[idx];
    float4 o;
#define GRU1(comp) { \
    float r = 1.f / (1.f + __expf(-(ir.comp + hr.comp))); \
    float z = 1.f / (1.f + __expf(-(iz.comp + hz.comp))); \
    float n = tanhf(in.comp + r * hn.comp); \
    o.comp = (1.f - z) * n + z * mv.comp; }
    GRU1(x) GRU1(y) GRU1(z) GRU1(w)
#undef GRU1
    ((float4*)mout)[idx] = o;
    bf16 hx, lx, hy, ly, hz2, lz2, hw, lw;
    split1(o.x, hx, lx); split1(o.y, hy, ly);
    split1(o.z, hz2, lz2); split1(o.w, hw, lw);
    bf162 p01, p23, q01, q23;
    p01.x = hx; p01.y = hy; p23.x = hz2; p23.y = hw;
    q01.x = lx; q01.y = ly; q23.x = lz2; q23.y = lw;
    size_t bo = (size_t)idx * 4;
    *(bf162*)(mh + bo)     = p01;
    *(bf162*)(mh + bo + 2) = p23;
    *(bf162*)(ml + bo)     = q01;
    *(bf162*)(ml + bo + 2) = q23;
    if (mode == 1) {
        float4 tv = ((const float4*)tot)[idx];
        tv.x += o.x; tv.y += o.y; tv.z += o.z; tv.w += o.w;
        ((float4*)tot)[idx] = tv;
    } else if (mode == 2) {
        ((float4*)tot)[idx] = o;
    }
}

// ---------------- LayerNorm(h+tot)*g+b, ReLU (+ bf16 split) ------------------
__global__ void k_ln(float* __restrict__ h, const float* __restrict__ tot,
                     const float* __restrict__ g, const float* __restrict__ b,
                     bf16* __restrict__ hh, bf16* __restrict__ hl) {
    int i = blockIdx.x * 8 + (threadIdx.x >> 5);
    int lane = threadIdx.x & 31;
    if (i >= N_NODES) return;
    float4 hv = ((float4*)(h + (size_t)i * C))[lane];
    float4 tv = ((const float4*)(tot + (size_t)i * C))[lane];
    float4 v = make_float4(hv.x + tv.x, hv.y + tv.y, hv.z + tv.z, hv.w + tv.w);
    float s  = v.x + v.y + v.z + v.w;
    float ss = v.x * v.x + v.y * v.y + v.z * v.z + v.w * v.w;
#pragma unroll
    for (int off = 16; off; off >>= 1) {
        s  += __shfl_xor_sync(0xffffffffu, s, off);
        ss += __shfl_xor_sync(0xffffffffu, ss, off);
    }
    float mu  = s * (1.f / 128.f);
    float var = ss * (1.f / 128.f) - mu * mu;
    float inv = rsqrtf(var + 1e-5f);
    float4 gg = ((const float4*)g)[lane];
    float4 bb = ((const float4*)b)[lane];
    float4 o;
    o.x = fmaxf((v.x - mu) * inv * gg.x + bb.x, 0.f);
    o.y = fmaxf((v.y - mu) * inv * gg.y + bb.y, 0.f);
    o.z = fmaxf((v.z - mu) * inv * gg.z + bb.z, 0.f);
    o.w = fmaxf((v.w - mu) * inv * gg.w + bb.w, 0.f);
    ((float4*)(h + (size_t)i * C))[lane] = o;
    bf16 hx, lx, hy, ly, hz, lz, hw, lw;
    split1(o.x, hx, lx); split1(o.y, hy, ly);
    split1(o.z, hz, lz); split1(o.w, hw, lw);
    bf162 p01, p23, q01, q23;
    p01.x = hx; p01.y = hy; p23.x = hz; p23.y = hw;
    q01.x = lx; q01.y = ly; q23.x = lz; q23.y = lw;
    size_t bo = (size_t)i * C + lane * 4;
    *(bf162*)(hh + bo)     = p01;
    *(bf162*)(hh + bo + 2) = p23;
    *(bf162*)(hl + bo)     = q01;
    *(bf162*)(hl + bo + 2) = q23;
}

// ---------------- head second layer (warp per node) --------------------------
__global__ void k_head2(const float* __restrict__ z, const float* __restrict__ w2,
                        const float* __restrict__ b2, float* __restrict__ out) {
    int i = blockIdx.x * 8 + (threadIdx.x >> 5);
    int lane = threadIdx.x & 31;
    if (i >= N_NODES) return;
    float4 zv = ((const float4*)(z + (size_t)i * C))[lane];
    float4 w0 = ((const float4*)w2)[lane];
    float4 w1 = ((const float4*)(w2 + C))[lane];
    float d0 = zv.x * w0.x + zv.y * w0.y + zv.z * w0.z + zv.w * w0.w;
    float d1 = zv.x * w1.x + zv.y * w1.y + zv.z * w1.z + zv.w * w1.w;
#pragma unroll
    for (int off = 16; off; off >>= 1) {
        d0 += __shfl_xor_sync(0xffffffffu, d0, off);
        d1 += __shfl_xor_sync(0xffffffffu, d1, off);
    }
    if (lane == 0) {
        out[(size_t)i * 2 + 0] = d0 + b2[0];
        out[(size_t)i * 2 + 1] = d1 + b2[1];
    }
}

// ---------------- driver -----------------------------------------------------
extern "C" void kernel_launch(void* const* d_in, const int* in_sizes, int n_in,
                              void* d_out, int out_size) {
    const int*   x_type     = (const int*)d_in[0];
    const int*   x_tok      = (const int*)d_in[1];
    const float* x_small    = (const float*)d_in[2];
    const int*   edge_index = (const int*)d_in[3];
    const int*   edge_type  = (const int*)d_in[4];
    const float* conv_w     = (const float*)d_in[5];
    const float* gru_wih    = (const float*)d_in[6];
    const float* gru_whh    = (const float*)d_in[7];
    const float* gru_bih    = (const float*)d_in[8];
    const float* gru_bhh    = (const float*)d_in[9];
    const float* ln_g       = (const float*)d_in[10];
    const float* ln_b       = (const float*)d_in[11];
    const float* head_w1    = (const float*)d_in[12];
    const float* head_b1    = (const float*)d_in[13];
    const float* head_w2    = (const float*)d_in[14];
    const float* head_b2    = (const float*)d_in[15];
    float* out = (float*)d_out;

    float *ph, *pm, *px, *ptot, *pgi, *pgh;
    bf16 *phh, *phl, *pmh, *pml, *pah, *pal;
    bf16 *pwch, *pwcl, *pwihh, *pwihl, *pwhhh, *pwhhl, *pw1h, *pw1l;
    int *pcnt, *pincl, *pcur, *pbsum, *pindptr, *peidx;
    cudaGetSymbolAddress((void**)&ph,   g_h);
    cudaGetSymbolAddress((void**)&pm,   g_m);
    cudaGetSymbolAddress((void**)&px,   g_x);
    cudaGetSymbolAddress((void**)&ptot, g_tot);
    cudaGetSymbolAddress((void**)&pgi,  g_gi);
    cudaGetSymbolAddress((void**)&pgh,  g_gh);
    cudaGetSymbolAddress((void**)&phh,  g_hh);
    cudaGetSymbolAddress((void**)&phl,  g_hl);
    cudaGetSymbolAddress((void**)&pmh,  g_mh);
    cudaGetSymbolAddress((void**)&pml,  g_ml);
    cudaGetSymbolAddress((void**)&pah,  g_ah);
    cudaGetSymbolAddress((void**)&pal,  g_al);
    cudaGetSymbolAddress((void**)&pwch, g_wch);
    cudaGetSymbolAddress((void**)&pwcl, g_wcl);
    cudaGetSymbolAddress((void**)&pwihh, g_wihh);
    cudaGetSymbolAddress((void**)&pwihl, g_wihl);
    cudaGetSymbolAddress((void**)&pwhhh, g_whhh);
    cudaGetSymbolAddress((void**)&pwhhl, g_whhl);
    cudaGetSymbolAddress((void**)&pw1h, g_w1h);
    cudaGetSymbolAddress((void**)&pw1l, g_w1l);
    cudaGetSymbolAddress((void**)&pcnt, g_cnt);
    cudaGetSymbolAddress((void**)&pincl, g_incl);
    cudaGetSymbolAddress((void**)&pcur, g_cur);
    cudaGetSymbolAddress((void**)&pbsum, g_bsum);
    cudaGetSymbolAddress((void**)&pindptr, g_indptr);
    cudaGetSymbolAddress((void**)&peidx, g_eidx);

    const int SMEMSZ = 4 * MAT_BYTES;   // 139264
    cudaFuncSetAttribute(k_mma2<false, false, 1>,
                         cudaFuncAttributeMaxDynamicSharedMemorySize, SMEMSZ);
    cudaFuncSetAttribute(k_mma2<true, false, 3>,
                         cudaFuncAttributeMaxDynamicSharedMemorySize, SMEMSZ);
    cudaFuncSetAttribute(k_mma2<true, true, 1>,
                         cudaFuncAttributeMaxDynamicSharedMemorySize, SMEMSZ);

    const int rowBlocks = (N_NODES + 127) / 128;    // 391
    const int n4 = NC / 4;
    const int warpGrid = (N_NODES + 7) / 8;
    const int SCANB = (M3 + 1023) / 1024;           // 147
    const int EG = (N_EDGES + 255) / 256;

    // ---- one-time per launch: features, weight split, CSR ----
    k_feat<<<N_NODES, 128>>>(x_type, x_tok, x_small, ph, phh, phl);
    k_cvt_tr<<<(18*C*C + 255)/256, 256>>>(conv_w, pwch, pwcl);
    k_cvtpair<<<(6*G3*C + 255)/256, 256>>>(gru_wih, pwihh, pwihl, 6*G3*C);
    k_cvtpair<<<(6*G3*C + 255)/256, 256>>>(gru_whh, pwhhh, pwhhl, 6*G3*C);
    k_cvtpair<<<(C*C + 255)/256, 256>>>(head_w1, pw1h, pw1l, C*C);

    k_izero<<<(M3 + 255)/256, 256>>>(pcnt, M3);
    k_count<<<EG, 256>>>(edge_index, edge_type, pcnt);
    k_scan1<<<SCANB, 1024>>>(pcnt, pincl, pbsum);
    k_scan2<<<1, 32>>>(pbsum, SCANB);
    k_scan3<<<SCANB, 1024>>>(pincl, pbsum, pindptr, pcur);
    k_curinit<<<(M3 + 255)/256, 256>>>(pindptr, pcur);
    k_fill<<<EG, 256>>>(edge_index, edge_type, pcur, peidx);

    for (int b = 0; b < 2; b++) {
        for (int t = 0; t < 3; t++) {
            for (int s = 0; s < 3; s++) {
                const bf16* Ah = (s == 0) ? phh : pmh;
                const bf16* Al = (s == 0) ? phl : pml;
                const float* hin = (s == 0) ? ph : pm;

                size_t wco = (size_t)(((b * 3 + t) * 3 + s)) * C * C;
                k_mma2<false, false, 1><<<rowBlocks, 256, SMEMSZ>>>(
                    Ah, Al, pwch + wco, pwcl + wco, nullptr, px);

                k_gather<<<warpGrid, 256>>>(px, peidx, pindptr, t, pah, pal);

                size_t wo = (size_t)(b * 3 + t) * G3 * C;
                const float* Bih = gru_bih + (size_t)(b * 3 + t) * G3;
                k_mma2<true, false, 3><<<rowBlocks, 256, SMEMSZ>>>(
                    pah, pal, pwihh + wo, pwihl + wo, Bih, pgi);

                const float* Bhh = gru_bhh + (size_t)(b * 3 + t) * G3;
                k_mma2<true, false, 3><<<rowBlocks, 256, SMEMSZ>>>(
                    Ah, Al, pwhhh + wo, pwhhl + wo, Bhh, pgh);

                int mode = (s == 2) ? ((t == 0) ? 2 : 1) : 0;
                k_gru<<<(n4 + 255) / 256, 256>>>(pgi, pgh, hin, pm, pmh, pml,
                                                 ptot, mode);
            }
        }
        k_ln<<<warpGrid, 256>>>(ph, ptot, ln_g + b * C, ln_b + b * C, phh, phl);
    }

    // head
    k_mma2<true, true, 1><<<rowBlocks, 256, SMEMSZ>>>(
        phh, phl, pw1h, pw1l, head_b1, px);
    k_head2<<<warpGrid, 256>>>(px, head_w2, head_b2, out);
}

// round 6
// speedup vs baseline: 2.3644x; 1.0253x over previous
#include <cuda_runtime.h>
#include <cuda_bf16.h>
#include <math.h>
#include <stdint.h>

#define N_NODES 50000
#define N_EDGES 500000
#define C 128
#define G3 384
#define NC (N_NODES*C)
#define M3 (3*N_NODES)

typedef __nv_bfloat16 bf16;
typedef __nv_bfloat162 bf162;

// ---------------- scratch (device globals) -----------------------------------
__device__ float g_h[NC];
__device__ float g_x[NC];
__device__ float g_tot[NC];
__device__ bf16  g_hh[NC], g_hl[NC];
__device__ bf16  g_mh[NC], g_ml[NC];
__device__ bf16  g_ah[NC], g_al[NC];
// weights (bf16 hi/lo, B as [n][k])
__device__ bf16  g_wch[18*C*C], g_wcl[18*C*C];
__device__ bf16  g_wihh[6*G3*C], g_wihl[6*G3*C];
__device__ bf16  g_whhh[6*G3*C], g_whhl[6*G3*C];
__device__ bf16  g_w1h[C*C], g_w1l[C*C];
// CSR
__device__ int g_cnt[M3], g_incl[M3], g_cur[M3], g_bsum[256];
__device__ int g_indptr[M3+1];
__device__ int g_eidx[N_EDGES];

// ---------------- helpers ----------------------------------------------------
__device__ __forceinline__ uint32_t smem_u32(const void* p) {
    uint32_t a;
    asm("{ .reg .u64 t; cvta.to.shared.u64 t, %1; cvt.u32.u64 %0, t; }"
        : "=r"(a) : "l"(p));
    return a;
}

#define LDSM4(r, addr) \
    asm volatile("ldmatrix.sync.aligned.m8n8.x4.shared.b16 {%0,%1,%2,%3}, [%4];" \
        : "=r"((r)[0]), "=r"((r)[1]), "=r"((r)[2]), "=r"((r)[3]) : "r"(addr))

#define MMA(d, a, b) \
    asm volatile("mma.sync.aligned.m16n8k16.row.col.f32.bf16.bf16.f32 " \
        "{%0,%1,%2,%3}, {%4,%5,%6,%7}, {%8,%9}, {%0,%1,%2,%3};" \
        : "+f"((d)[0]), "+f"((d)[1]), "+f"((d)[2]), "+f"((d)[3]) \
        : "r"((a)[0]), "r"((a)[1]), "r"((a)[2]), "r"((a)[3]), \
          "r"((b)[0]), "r"((b)[1]))

__device__ __forceinline__ void split1(float v, bf16& h, bf16& l) {
    h = __float2bfloat16(v);
    l = __float2bfloat16(v - __bfloat162float(h));
}

#define TS 136
#define MAT_BYTES (128 * TS * 2)   // 34816
#define A64_BYTES (64 * TS * 2)    // 17408

// 32m x 32n warp-tile GEMM over one staged 128-col block.
// A: 64 rows (hi/lo), B: 128 n-rows (hi/lo). 3-term bf16 compensation.
__device__ __forceinline__ void gemm_tile32(uint32_t uAH, uint32_t uAL,
                                            uint32_t uBH, uint32_t uBL,
                                            int m0, int n0, int lane,
                                            float acc[2][4][4]) {
#pragma unroll
    for (int mi = 0; mi < 2; mi++)
#pragma unroll
        for (int nj = 0; nj < 4; nj++)
#pragma unroll
            for (int q = 0; q < 4; q++) acc[mi][nj][q] = 0.f;

    const int arow = lane & 15;
    const int acol = (lane >> 4) << 3;
    const int brow = (lane & 7) + ((lane >> 4) << 3);
    const int bcol = ((lane >> 3) & 1) << 3;

#pragma unroll
    for (int ks = 0; ks < 8; ks++) {
        const int k = ks * 16;
        uint32_t ah[2][4], al[2][4];
#pragma unroll
        for (int mi = 0; mi < 2; mi++) {
            uint32_t off = (uint32_t)(((m0 + mi * 16 + arow) * TS + k + acol) * 2);
            LDSM4(ah[mi], uAH + off);
            LDSM4(al[mi], uAL + off);
        }
        uint32_t bh[4][2], bl[4][2];
#pragma unroll
        for (int nq = 0; nq < 2; nq++) {
            uint32_t off = (uint32_t)(((n0 + nq * 16 + brow) * TS + k + bcol) * 2);
            uint32_t r4[4];
            LDSM4(r4, uBH + off);
            bh[2*nq][0]=r4[0]; bh[2*nq][1]=r4[1]; bh[2*nq+1][0]=r4[2]; bh[2*nq+1][1]=r4[3];
            LDSM4(r4, uBL + off);
            bl[2*nq][0]=r4[0]; bl[2*nq][1]=r4[1]; bl[2*nq+1][0]=r4[2]; bl[2*nq+1][1]=r4[3];
        }
#pragma unroll
        for (int mi = 0; mi < 2; mi++)
#pragma unroll
            for (int nj = 0; nj < 4; nj++) {
                MMA(acc[mi][nj], ah[mi], bh[nj]);
                MMA(acc[mi][nj], ah[mi], bl[nj]);
                MMA(acc[mi][nj], al[mi], bh[nj]);
            }
    }
}

// ---------------- fused gi/gh GEMM + GRU kernel ------------------------------
// 64-row tile. A1 = agg (gi input), A2 = m (gh input, also GRU state).
// For blk in {r,z,n}: acc_gi = A1 @ wih_blk^T, acc_gh = A2 @ whh_blk^T,
// combine gates in registers. m' written as bf16 hi/lo; tot per mode.
// SMEM: A1h|A1l|A2h|A2l (4x17408) | Bh|Bl (2x34816) = 139264.
__global__ void __launch_bounds__(256, 1)
k_gates(const bf16* __restrict__ aggh, const bf16* __restrict__ aggl,
        const bf16* __restrict__ a2h,  const bf16* __restrict__ a2l,
        const bf16* __restrict__ wihh, const bf16* __restrict__ wihl,
        const bf16* __restrict__ whhh, const bf16* __restrict__ whhl,
        const float* __restrict__ bih, const float* __restrict__ bhh,
        bf16* __restrict__ mh_out, bf16* __restrict__ ml_out,
        float* __restrict__ tot, int mode) {
    extern __shared__ char sm[];
    bf16* A1H = (bf16*)(sm);
    bf16* A1L = (bf16*)(sm + A64_BYTES);
    bf16* A2H = (bf16*)(sm + 2 * A64_BYTES);
    bf16* A2L = (bf16*)(sm + 3 * A64_BYTES);
    bf16* BH  = (bf16*)(sm + 4 * A64_BYTES);
    bf16* BL  = (bf16*)(sm + 4 * A64_BYTES + MAT_BYTES);

    const int tid  = threadIdx.x;
    const int row0 = blockIdx.x * 64;

    // stage A1, A2 (hi/lo), 1024 granules of 8 bf16
#pragma unroll
    for (int i = 0; i < 4; i++) {
        int g = tid + i * 256;
        int r = g >> 4, k8 = (g & 15) * 8;
        uint4 v1h = make_uint4(0,0,0,0), v1l = v1h, v2h = v1h, v2l = v1h;
        if (row0 + r < N_NODES) {
            size_t o = (size_t)(row0 + r) * C + k8;
            v1h = *(const uint4*)(aggh + o);
            v1l = *(const uint4*)(aggl + o);
            v2h = *(const uint4*)(a2h + o);
            v2l = *(const uint4*)(a2l + o);
        }
        int so = r * TS + k8;
        *(uint4*)(A1H + so) = v1h;
        *(uint4*)(A1L + so) = v1l;
        *(uint4*)(A2H + so) = v2h;
        *(uint4*)(A2L + so) = v2l;
    }

    const int wid  = tid >> 5, lane = tid & 31;
    const int m0 = (wid & 1) * 32;        // 2 m-warps
    const int n0 = (wid >> 1) * 32;       // 4 n-warps
    const uint32_t uA1H = smem_u32(A1H), uA1L = smem_u32(A1L);
    const uint32_t uA2H = smem_u32(A2H), uA2L = smem_u32(A2L);
    const uint32_t uBH  = smem_u32(BH),  uBL  = smem_u32(BL);

    float rg[2][4][4], zg[2][4][4];

#pragma unroll
    for (int blk = 0; blk < 3; blk++) {
        float acc_i[2][4][4], acc_h[2][4][4];
        // ---- gi_blk ----
        __syncthreads();
#pragma unroll
        for (int i = 0; i < 8; i++) {
            int g = tid + i * 256;
            int n = g >> 4, k8 = (g & 15) * 8;
            size_t o = (size_t)(blk * 128 + n) * C + k8;
            *(uint4*)(BH + n * TS + k8) = *(const uint4*)(wihh + o);
            *(uint4*)(BL + n * TS + k8) = *(const uint4*)(wihl + o);
        }
        __syncthreads();
        gemm_tile32(uA1H, uA1L, uBH, uBL, m0, n0, lane, acc_i);

        // ---- gh_blk ----
        __syncthreads();
#pragma unroll
        for (int i = 0; i < 8; i++) {
            int g = tid + i * 256;
            int n = g >> 4, k8 = (g & 15) * 8;
            size_t o = (size_t)(blk * 128 + n) * C + k8;
            *(uint4*)(BH + n * TS + k8) = *(const uint4*)(whhh + o);
            *(uint4*)(BL + n * TS + k8) = *(const uint4*)(whhl + o);
        }
        __syncthreads();
        gemm_tile32(uA2H, uA2L, uBH, uBL, m0, n0, lane, acc_h);

        // ---- combine ----
        if (blk == 0 || blk == 1) {
#pragma unroll
            for (int mi = 0; mi < 2; mi++)
#pragma unroll
                for (int nj = 0; nj < 4; nj++) {
                    int c = blk * 128 + n0 + nj * 8 + (lane & 3) * 2;
                    float bi0 = bih[c], bi1 = bih[c + 1];
                    float bh0 = bhh[c], bh1 = bhh[c + 1];
#pragma unroll
                    for (int q = 0; q < 4; q++) {
                        float pre = acc_i[mi][nj][q] + ((q & 1) ? bi1 : bi0)
                                  + acc_h[mi][nj][q] + ((q & 1) ? bh1 : bh0);
                        float gv = 1.f / (1.f + __expf(-pre));
                        if (blk == 0) rg[mi][nj][q] = gv;
                        else          zg[mi][nj][q] = gv;
                    }
                }
        } else {
            // n-gate + GRU output
#pragma unroll
            for (int mi = 0; mi < 2; mi++)
#pragma unroll
                for (int nj = 0; nj < 4; nj++) {
                    int mc = n0 + nj * 8 + (lane & 3) * 2;   // m column
                    int c = 256 + mc;
                    float bi0 = bih[c], bi1 = bih[c + 1];
                    float bh0 = bhh[c], bh1 = bhh[c + 1];
                    float o2[4];
#pragma unroll
                    for (int q = 0; q < 4; q++) {
                        int rl = m0 + mi * 16 + (lane >> 2) + (q >> 1) * 8;
                        int cc = mc + (q & 1);
                        float pi = acc_i[mi][nj][q] + ((q & 1) ? bi1 : bi0);
                        float phv = acc_h[mi][nj][q] + ((q & 1) ? bh1 : bh0);
                        float n = tanhf(pi + rg[mi][nj][q] * phv);
                        float z = zg[mi][nj][q];
                        float mv = __bfloat162float(A2H[rl * TS + cc])
                                 + __bfloat162float(A2L[rl * TS + cc]);
                        o2[q] = (1.f - z) * n + z * mv;
                    }
                    // write two rows x bf162 (hi/lo), + tot
#pragma unroll
                    for (int h2 = 0; h2 < 2; h2++) {
                        int gr = row0 + m0 + mi * 16 + (lane >> 2) + h2 * 8;
                        if (gr >= N_NODES) continue;
                        float v0 = o2[h2 * 2], v1 = o2[h2 * 2 + 1];
                        bf16 h0, l0, h1, l1;
                        split1(v0, h0, l0); split1(v1, h1, l1);
                        bf162 ph2; ph2.x = h0; ph2.y = h1;
                        bf162 pl2; pl2.x = l0; pl2.y = l1;
                        size_t go = (size_t)gr * C + mc;
                        *(bf162*)(mh_out + go) = ph2;
                        *(bf162*)(ml_out + go) = pl2;
                        if (mode == 1) {
                            float2 tv = *(float2*)(tot + go);
                            tv.x += v0; tv.y += v1;
                            *(float2*)(tot + go) = tv;
                        } else if (mode == 2) {
                            float2 tv; tv.x = v0; tv.y = v1;
                            *(float2*)(tot + go) = tv;
                        }
                    }
                }
        }
    }
}

// ---------------- weight conversion ------------------------------------------
__global__ void k_cvtpair(const float* __restrict__ in, bf16* __restrict__ oh,
                          bf16* __restrict__ ol, int n) {
    int i = blockIdx.x * 256 + threadIdx.x;
    if (i >= n) return;
    bf16 h, l; split1(in[i], h, l);
    oh[i] = h; ol[i] = l;
}

// conv_w [18][k][n] -> [18][n][k] hi/lo
__global__ void k_cvt_tr(const float* __restrict__ in, bf16* __restrict__ oh,
                         bf16* __restrict__ ol) {
    int idx = blockIdx.x * 256 + threadIdx.x;
    if (idx >= 18 * C * C) return;
    int w = idx >> 14, rem = idx & 16383;
    int nn = rem >> 7, kk = rem & 127;
    float v = in[(w << 14) + (kk << 7) + nn];
    bf16 h, l; split1(v, h, l);
    oh[idx] = h; ol[idx] = l;
}

// ---------------- CSR build --------------------------------------------------
__global__ void k_izero(int* __restrict__ p, int n) {
    int i = blockIdx.x * 256 + threadIdx.x;
    if (i < n) p[i] = 0;
}
__global__ void k_count(const int* __restrict__ ei, const int* __restrict__ et,
                        int* __restrict__ cnt) {
    int e = blockIdx.x * 256 + threadIdx.x;
    if (e >= N_EDGES) return;
    atomicAdd(cnt + et[e] * N_NODES + ei[N_EDGES + e], 1);
}
__global__ void k_scan1(const int* __restrict__ cnt, int* __restrict__ incl,
                        int* __restrict__ bsum) {
    __shared__ int sm[1024];
    int i = blockIdx.x * 1024 + threadIdx.x;
    int v = (i < M3) ? cnt[i] : 0;
    sm[threadIdx.x] = v;
    __syncthreads();
#pragma unroll
    for (int off = 1; off < 1024; off <<= 1) {
        int t = (threadIdx.x >= off) ? sm[threadIdx.x - off] : 0;
        __syncthreads();
        sm[threadIdx.x] += t;
        __syncthreads();
    }
    if (i < M3) incl[i] = sm[threadIdx.x];
    if (threadIdx.x == 1023) bsum[blockIdx.x] = sm[1023];
}
__global__ void k_scan2(int* __restrict__ bsum, int nb) {
    if (blockIdx.x == 0 && threadIdx.x == 0) {
        int acc = 0;
        for (int b = 0; b < nb; b++) { int v = bsum[b]; bsum[b] = acc; acc += v; }
    }
}
__global__ void k_scan3(const int* __restrict__ incl, const int* __restrict__ bsum,
                        int* __restrict__ indptr) {
    int i = blockIdx.x * 1024 + threadIdx.x;
    if (i < M3) indptr[i + 1] = incl[i] + bsum[blockIdx.x];
    if (i == 0) indptr[0] = 0;
}
__global__ void k_curinit(const int* __restrict__ indptr, int* __restrict__ cur) {
    int i = blockIdx.x * 256 + threadIdx.x;
    if (i < M3) cur[i] = indptr[i];
}
__global__ void k_fill(const int* __restrict__ ei, const int* __restrict__ et,
                       int* __restrict__ cur, int* __restrict__ eidx) {
    int e = blockIdx.x * 256 + threadIdx.x;
    if (e >= N_EDGES) return;
    int tn = et[e] * N_NODES + ei[N_EDGES + e];
    int p = atomicAdd(cur + tn, 1);
    eidx[p] = ei[e];
}

// ---------------- gather: agg[dst] = sum x[src], bf16 hi/lo out --------------
__global__ void k_gather(const float* __restrict__ x, const int* __restrict__ eidx,
                         const int* __restrict__ indptr, int t,
                         bf16* __restrict__ aggh, bf16* __restrict__ aggl) {
    int w = blockIdx.x * 8 + (threadIdx.x >> 5);
    int lane = threadIdx.x & 31;
    if (w >= N_NODES) return;
    int tn = t * N_NODES + w;
    int beg = indptr[tn], end = indptr[tn + 1];
    float4 s = make_float4(0.f, 0.f, 0.f, 0.f);
    for (int j = beg; j < end; j++) {
        int src = eidx[j];
        float4 v = ((const float4*)x)[src * 32 + lane];
        s.x += v.x; s.y += v.y; s.z += v.z; s.w += v.w;
    }
    bf16 hx, lx, hy, ly, hz, lz, hw, lw;
    split1(s.x, hx, lx); split1(s.y, hy, ly);
    split1(s.z, hz, lz); split1(s.w, hw, lw);
    bf162 h01; h01.x = hx; h01.y = hy;
    bf162 h23; h23.x = hz; h23.y = hw;
    bf162 l01; l01.x = lx; l01.y = ly;
    bf162 l23; l23.x = lz; l23.y = lw;
    size_t o = (size_t)w * C + lane * 4;
    *(bf162*)(aggh + o)     = h01;
    *(bf162*)(aggh + o + 2) = h23;
    *(bf162*)(aggl + o)     = l01;
    *(bf162*)(aggl + o + 2) = l23;
}

// ---------------- conv / head GEMM (128-row tile, NB=1) ----------------------
template<bool BIAS, bool RELU>
__global__ void __launch_bounds__(256, 1)
k_mma2(const bf16* __restrict__ Ah, const bf16* __restrict__ Al,
       const bf16* __restrict__ Wh, const bf16* __restrict__ Wl,
       const float* __restrict__ bias, float* __restrict__ Y) {
    extern __shared__ char sm[];
    bf16* AH = (bf16*)(sm);
    bf16* AL = (bf16*)(sm + MAT_BYTES);
    bf16* BH = (bf16*)(sm + 2 * MAT_BYTES);
    bf16* BL = (bf16*)(sm + 3 * MAT_BYTES);

    const int tid  = threadIdx.x;
    const int row0 = blockIdx.x * 128;

#pragma unroll
    for (int i = 0; i < 8; i++) {
        int g = tid + i * 256;
        int r = g >> 4, k8 = (g & 15) * 8;
        uint4 vh = make_uint4(0u, 0u, 0u, 0u), vl = vh;
        if (row0 + r < N_NODES) {
            vh = *(const uint4*)(Ah + (size_t)(row0 + r) * C + k8);
            vl = *(const uint4*)(Al + (size_t)(row0 + r) * C + k8);
        }
        *(uint4*)(AH + r * TS + k8) = vh;
        *(uint4*)(AL + r * TS + k8) = vl;
        *(uint4*)(BH + r * TS + k8) = *(const uint4*)(Wh + (size_t)r * C + k8);
        *(uint4*)(BL + r * TS + k8) = *(const uint4*)(Wl + (size_t)r * C + k8);
    }
    __syncthreads();

    const int wid  = tid >> 5, lane = tid & 31;
    const int m0 = (wid & 3) * 32;
    const int n0 = (wid >> 2) * 64;
    const int arow = lane & 15;
    const int acol = (lane >> 4) << 3;
    const int brow = (lane & 7) + ((lane >> 4) << 3);
    const int bcol = ((lane >> 3) & 1) << 3;
    const uint32_t uAH = smem_u32(AH), uAL = smem_u32(AL);
    const uint32_t uBH = smem_u32(BH), uBL = smem_u32(BL);

    float acc[2][8][4];
#pragma unroll
    for (int mi = 0; mi < 2; mi++)
#pragma unroll
        for (int nj = 0; nj < 8; nj++)
#pragma unroll
            for (int q = 0; q < 4; q++) acc[mi][nj][q] = 0.f;

#pragma unroll
    for (int ks = 0; ks < 8; ks++) {
        const int k = ks * 16;
        uint32_t ah[2][4], al[2][4];
#pragma unroll
        for (int mi = 0; mi < 2; mi++) {
            uint32_t off = (uint32_t)(((m0 + mi * 16 + arow) * TS + k + acol) * 2);
            LDSM4(ah[mi], uAH + off);
            LDSM4(al[mi], uAL + off);
        }
        uint32_t bh[8][2], bl[8][2];
#pragma unroll
        for (int nq = 0; nq < 4; nq++) {
            uint32_t off = (uint32_t)(((n0 + nq * 16 + brow) * TS + k + bcol) * 2);
            uint32_t r4[4];
            LDSM4(r4, uBH + off);
            bh[2*nq][0]=r4[0]; bh[2*nq][1]=r4[1]; bh[2*nq+1][0]=r4[2]; bh[2*nq+1][1]=r4[3];
            LDSM4(r4, uBL + off);
            bl[2*nq][0]=r4[0]; bl[2*nq][1]=r4[1]; bl[2*nq+1][0]=r4[2]; bl[2*nq+1][1]=r4[3];
        }
#pragma unroll
        for (int mi = 0; mi < 2; mi++)
#pragma unroll
            for (int nj = 0; nj < 8; nj++) {
                MMA(acc[mi][nj], ah[mi], bh[nj]);
                MMA(acc[mi][nj], ah[mi], bl[nj]);
                MMA(acc[mi][nj], al[mi], bh[nj]);
            }
    }

    const int rbase = row0 + m0 + (lane >> 2);
    const int cbase = n0 + (lane & 3) * 2;
#pragma unroll
    for (int mi = 0; mi < 2; mi++) {
#pragma unroll
        for (int nj = 0; nj < 8; nj++) {
            int gr = rbase + mi * 16;
            int gc = cbase + nj * 8;
            float b0 = 0.f, b1 = 0.f;
            if (BIAS) { b0 = bias[gc]; b1 = bias[gc + 1]; }
            float2 v0, v1;
            v0.x = acc[mi][nj][0] + b0; v0.y = acc[mi][nj][1] + b1;
            v1.x = acc[mi][nj][2] + b0; v1.y = acc[mi][nj][3] + b1;
            if (RELU) {
                v0.x = fmaxf(v0.x, 0.f); v0.y = fmaxf(v0.y, 0.f);
                v1.x = fmaxf(v1.x, 0.f); v1.y = fmaxf(v1.y, 0.f);
            }
            if (gr < N_NODES)
                *(float2*)(Y + (size_t)gr * C + gc) = v0;
            if (gr + 8 < N_NODES)
                *(float2*)(Y + (size_t)(gr + 8) * C + gc) = v1;
        }
    }
}

// ---------------- feature build (fp32 + bf16 hi/lo) --------------------------
__global__ void k_feat(const int* __restrict__ xt, const int* __restrict__ xk,
                       const float* __restrict__ xs, float* __restrict__ h,
                       bf16* __restrict__ hh, bf16* __restrict__ hl) {
    int i = blockIdx.x;
    int c = threadIdx.x;
    int t = xt[i];
    int k = xk[i];
    k = min(max(k, 0), 93);
    float v;
    if (c < 32)       v = (c == t) ? 1.f : 0.f;
    else if (c < 126) v = ((c - 32) == k) ? 1.f : 0.f;
    else              v = xs[i * 2 + (c - 126)];
    size_t o = (size_t)i * C + c;
    h[o] = v;
    bf16 bh, bl; split1(v, bh, bl);
    hh[o] = bh; hl[o] = bl;
}

// ---------------- LayerNorm(h+tot)*g+b, ReLU (+ bf16 split) ------------------
__global__ void k_ln(float* __restrict__ h, const float* __restrict__ tot,
                     const float* __restrict__ g, const float* __restrict__ b,
                     bf16* __restrict__ hh, bf16* __restrict__ hl) {
    int i = blockIdx.x * 8 + (threadIdx.x >> 5);
    int lane = threadIdx.x & 31;
    if (i >= N_NODES) return;
    float4 hv = ((float4*)(h + (size_t)i * C))[lane];
    float4 tv = ((const float4*)(tot + (size_t)i * C))[lane];
    float4 v = make_float4(hv.x + tv.x, hv.y + tv.y, hv.z + tv.z, hv.w + tv.w);
    float s  = v.x + v.y + v.z + v.w;
    float ss = v.x * v.x + v.y * v.y + v.z * v.z + v.w * v.w;
#pragma unroll
    for (int off = 16; off; off >>= 1) {
        s  += __shfl_xor_sync(0xffffffffu, s, off);
        ss += __shfl_xor_sync(0xffffffffu, ss, off);
    }
    float mu  = s * (1.f / 128.f);
    float var = ss * (1.f / 128.f) - mu * mu;
    float inv = rsqrtf(var + 1e-5f);
    float4 gg = ((const float4*)g)[lane];
    float4 bb = ((const float4*)b)[lane];
    float4 o;
    o.x = fmaxf((v.x - mu) * inv * gg.x + bb.x, 0.f);
    o.y = fmaxf((v.y - mu) * inv * gg.y + bb.y, 0.f);
    o.z = fmaxf((v.z - mu) * inv * gg.z + bb.z, 0.f);
    o.w = fmaxf((v.w - mu) * inv * gg.w + bb.w, 0.f);
    ((float4*)(h + (size_t)i * C))[lane] = o;
    bf16 hx, lx, hy, ly, hz, lz, hw, lw;
    split1(o.x, hx, lx); split1(o.y, hy, ly);
    split1(o.z, hz, lz); split1(o.w, hw, lw);
    bf162 p01, p23, q01, q23;
    p01.x = hx; p01.y = hy; p23.x = hz; p23.y = hw;
    q01.x = lx; q01.y = ly; q23.x = lz; q23.y = lw;
    size_t bo = (size_t)i * C + lane * 4;
    *(bf162*)(hh + bo)     = p01;
    *(bf162*)(hh + bo + 2) = p23;
    *(bf162*)(hl + bo)     = q01;
    *(bf162*)(hl + bo + 2) = q23;
}

// ---------------- head second layer (warp per node) --------------------------
__global__ void k_head2(const float* __restrict__ z, const float* __restrict__ w2,
                        const float* __restrict__ b2, float* __restrict__ out) {
    int i = blockIdx.x * 8 + (threadIdx.x >> 5);
    int lane = threadIdx.x & 31;
    if (i >= N_NODES) return;
    float4 zv = ((const float4*)(z + (size_t)i * C))[lane];
    float4 w0 = ((const float4*)w2)[lane];
    float4 w1 = ((const float4*)(w2 + C))[lane];
    float d0 = zv.x * w0.x + zv.y * w0.y + zv.z * w0.z + zv.w * w0.w;
    float d1 = zv.x * w1.x + zv.y * w1.y + zv.z * w1.z + zv.w * w1.w;
#pragma unroll
    for (int off = 16; off; off >>= 1) {
        d0 += __shfl_xor_sync(0xffffffffu, d0, off);
        d1 += __shfl_xor_sync(0xffffffffu, d1, off);
    }
    if (lane == 0) {
        out[(size_t)i * 2 + 0] = d0 + b2[0];
        out[(size_t)i * 2 + 1] = d1 + b2[1];
    }
}

// ---------------- driver -----------------------------------------------------
extern "C" void kernel_launch(void* const* d_in, const int* in_sizes, int n_in,
                              void* d_out, int out_size) {
    const int*   x_type     = (const int*)d_in[0];
    const int*   x_tok      = (const int*)d_in[1];
    const float* x_small    = (const float*)d_in[2];
    const int*   edge_index = (const int*)d_in[3];
    const int*   edge_type  = (const int*)d_in[4];
    const float* conv_w     = (const float*)d_in[5];
    const float* gru_wih    = (const float*)d_in[6];
    const float* gru_whh    = (const float*)d_in[7];
    const float* gru_bih    = (const float*)d_in[8];
    const float* gru_bhh    = (const float*)d_in[9];
    const float* ln_g       = (const float*)d_in[10];
    const float* ln_b       = (const float*)d_in[11];
    const float* head_w1    = (const float*)d_in[12];
    const float* head_b1    = (const float*)d_in[13];
    const float* head_w2    = (const float*)d_in[14];
    const float* head_b2    = (const float*)d_in[15];
    float* out = (float*)d_out;

    float *ph, *px, *ptot;
    bf16 *phh, *phl, *pmh, *pml, *pah, *pal;
    bf16 *pwch, *pwcl, *pwihh, *pwihl, *pwhhh, *pwhhl, *pw1h, *pw1l;
    int *pcnt, *pincl, *pcur, *pbsum, *pindptr, *peidx;
    cudaGetSymbolAddress((void**)&ph,   g_h);
    cudaGetSymbolAddress((void**)&px,   g_x);
    cudaGetSymbolAddress((void**)&ptot, g_tot);
    cudaGetSymbolAddress((void**)&phh,  g_hh);
    cudaGetSymbolAddress((void**)&phl,  g_hl);
    cudaGetSymbolAddress((void**)&pmh,  g_mh);
    cudaGetSymbolAddress((void**)&pml,  g_ml);
    cudaGetSymbolAddress((void**)&pah,  g_ah);
    cudaGetSymbolAddress((void**)&pal,  g_al);
    cudaGetSymbolAddress((void**)&pwch, g_wch);
    cudaGetSymbolAddress((void**)&pwcl, g_wcl);
    cudaGetSymbolAddress((void**)&pwihh, g_wihh);
    cudaGetSymbolAddress((void**)&pwihl, g_wihl);
    cudaGetSymbolAddress((void**)&pwhhh, g_whhh);
    cudaGetSymbolAddress((void**)&pwhhl, g_whhl);
    cudaGetSymbolAddress((void**)&pw1h, g_w1h);
    cudaGetSymbolAddress((void**)&pw1l, g_w1l);
    cudaGetSymbolAddress((void**)&pcnt, g_cnt);
    cudaGetSymbolAddress((void**)&pincl, g_incl);
    cudaGetSymbolAddress((void**)&pcur, g_cur);
    cudaGetSymbolAddress((void**)&pbsum, g_bsum);
    cudaGetSymbolAddress((void**)&pindptr, g_indptr);
    cudaGetSymbolAddress((void**)&peidx, g_eidx);

    const int SMEMSZ = 4 * MAT_BYTES;                       // 139264 (conv/head)
    const int GSMEM  = 4 * A64_BYTES + 2 * MAT_BYTES;       // 139264 (gates)
    cudaFuncSetAttribute(k_mma2<false, false>,
                         cudaFuncAttributeMaxDynamicSharedMemorySize, SMEMSZ);
    cudaFuncSetAttribute(k_mma2<true, true>,
                         cudaFuncAttributeMaxDynamicSharedMemorySize, SMEMSZ);
    cudaFuncSetAttribute(k_gates,
                         cudaFuncAttributeMaxDynamicSharedMemorySize, GSMEM);

    const int rowBlocks = (N_NODES + 127) / 128;    // 391
    const int rowBlocks64 = (N_NODES + 63) / 64;    // 782
    const int warpGrid = (N_NODES + 7) / 8;
    const int SCANB = (M3 + 1023) / 1024;           // 147
    const int EG = (N_EDGES + 255) / 256;

    // ---- one-time per launch: features, weight split, CSR ----
    k_feat<<<N_NODES, 128>>>(x_type, x_tok, x_small, ph, phh, phl);
    k_cvt_tr<<<(18*C*C + 255)/256, 256>>>(conv_w, pwch, pwcl);
    k_cvtpair<<<(6*G3*C + 255)/256, 256>>>(gru_wih, pwihh, pwihl, 6*G3*C);
    k_cvtpair<<<(6*G3*C + 255)/256, 256>>>(gru_whh, pwhhh, pwhhl, 6*G3*C);
    k_cvtpair<<<(C*C + 255)/256, 256>>>(head_w1, pw1h, pw1l, C*C);

    k_izero<<<(M3 + 255)/256, 256>>>(pcnt, M3);
    k_count<<<EG, 256>>>(edge_index, edge_type, pcnt);
    k_scan1<<<SCANB, 1024>>>(pcnt, pincl, pbsum);
    k_scan2<<<1, 32>>>(pbsum, SCANB);
    k_scan3<<<SCANB, 1024>>>(pincl, pbsum, pindptr);
    k_curinit<<<(M3 + 255)/256, 256>>>(pindptr, pcur);
    k_fill<<<EG, 256>>>(edge_index, edge_type, pcur, peidx);

    for (int b = 0; b < 2; b++) {
        for (int t = 0; t < 3; t++) {
            for (int s = 0; s < 3; s++) {
                const bf16* Ah = (s == 0) ? phh : pmh;
                const bf16* Al = (s == 0) ? phl : pml;

                size_t wco = (size_t)(((b * 3 + t) * 3 + s)) * C * C;
                k_mma2<false, false><<<rowBlocks, 256, SMEMSZ>>>(
                    Ah, Al, pwch + wco, pwcl + wco, nullptr, px);

                k_gather<<<warpGrid, 256>>>(px, peidx, pindptr, t, pah, pal);

                size_t wo = (size_t)(b * 3 + t) * G3 * C;
                const float* Bih = gru_bih + (size_t)(b * 3 + t) * G3;
                const float* Bhh = gru_bhh + (size_t)(b * 3 + t) * G3;
                int mode = (s == 2) ? ((t == 0) ? 2 : 1) : 0;
                k_gates<<<rowBlocks64, 256, GSMEM>>>(
                    pah, pal, Ah, Al,
                    pwihh + wo, pwihl + wo, pwhhh + wo, pwhhl + wo,
                    Bih, Bhh, pmh, pml, ptot, mode);
            }
        }
        k_ln<<<warpGrid, 256>>>(ph, ptot, ln_g + b * C, ln_b + b * C, phh, phl);
    }

    // head
    k_mma2<true, true><<<rowBlocks, 256, SMEMSZ>>>(
        phh, phl, pw1h, pw1l, head_b1, px);
    k_head2<<<warpGrid, 256>>>(px, head_w2, head_b2, out);
}

// round 7
// speedup vs baseline: 2.8175x; 1.1917x over previous
#include <cuda_runtime.h>
#include <cuda_bf16.h>
#include <math.h>
#include <stdint.h>

#define N_NODES 50000
#define N_EDGES 500000
#define C 128
#define G3 384
#define NC (N_NODES*C)
#define M3 (3*N_NODES)
#define FW (C*G3)            // 49152 per fused weight
#define CW (C*C)             // 16384 per conv weight

typedef __nv_bfloat16 bf16;
typedef __nv_bfloat162 bf162;

// ---------------- scratch (device globals) -----------------------------------
__device__ float g_h[NC];
__device__ float g_x[NC];
__device__ bf16  g_hh[NC], g_hl[NC];
__device__ bf16  g_mh[3*NC], g_ml[3*NC];     // per-type GRU state
__device__ bf16  g_ah[3*NC], g_al[3*NC];     // per-type gathered m
// weights
__device__ bf16  g_cwh[18*CW], g_cwl[18*CW];       // conv_w straight split [k][j]
__device__ bf16  g_wihh[6*G3*C], g_wihl[6*G3*C];   // wih [n][j]
__device__ bf16  g_whhh[6*G3*C], g_whhl[6*G3*C];   // whh [n][k]
__device__ bf16  g_w1h[CW], g_w1l[CW];
__device__ float g_F[18*FW];                        // F = convw @ wih^T  [k][n]
__device__ bf16  g_ffh[18*FW], g_ffl[18*FW];        // F n-major [n][k] hi/lo
// CSR
__device__ int g_cnt[M3], g_incl[M3], g_cur[M3], g_bsum[256];
__device__ int g_indptr[M3+1];
__device__ int g_eidx[N_EDGES];

// ---------------- helpers ----------------------------------------------------
__device__ __forceinline__ uint32_t smem_u32(const void* p) {
    uint32_t a;
    asm("{ .reg .u64 t; cvta.to.shared.u64 t, %1; cvt.u32.u64 %0, t; }"
        : "=r"(a) : "l"(p));
    return a;
}

#define LDSM4(r, addr) \
    asm volatile("ldmatrix.sync.aligned.m8n8.x4.shared.b16 {%0,%1,%2,%3}, [%4];" \
        : "=r"((r)[0]), "=r"((r)[1]), "=r"((r)[2]), "=r"((r)[3]) : "r"(addr))

#define MMA(d, a, b) \
    asm volatile("mma.sync.aligned.m16n8k16.row.col.f32.bf16.bf16.f32 " \
        "{%0,%1,%2,%3}, {%4,%5,%6,%7}, {%8,%9}, {%0,%1,%2,%3};" \
        : "+f"((d)[0]), "+f"((d)[1]), "+f"((d)[2]), "+f"((d)[3]) \
        : "r"((a)[0]), "r"((a)[1]), "r"((a)[2]), "r"((a)[3]), \
          "r"((b)[0]), "r"((b)[1]))

__device__ __forceinline__ void split1(float v, bf16& h, bf16& l) {
    h = __float2bfloat16(v);
    l = __float2bfloat16(v - __bfloat162float(h));
}

#define TS 136
#define MAT_BYTES (128 * TS * 2)   // 34816
#define A64_BYTES (64 * TS * 2)    // 17408

// 32m x 32n warp-tile GEMM over one staged 128-col block (A: 64 rows).
__device__ __forceinline__ void gemm_tile32(uint32_t uAH, uint32_t uAL,
                                            uint32_t uBH, uint32_t uBL,
                                            int m0, int n0, int lane,
                                            float acc[2][4][4]) {
#pragma unroll
    for (int mi = 0; mi < 2; mi++)
#pragma unroll
        for (int nj = 0; nj < 4; nj++)
#pragma unroll
            for (int q = 0; q < 4; q++) acc[mi][nj][q] = 0.f;

    const int arow = lane & 15;
    const int acol = (lane >> 4) << 3;
    const int brow = (lane & 7) + ((lane >> 4) << 3);
    const int bcol = ((lane >> 3) & 1) << 3;

#pragma unroll
    for (int ks = 0; ks < 8; ks++) {
        const int k = ks * 16;
        uint32_t ah[2][4], al[2][4];
#pragma unroll
        for (int mi = 0; mi < 2; mi++) {
            uint32_t off = (uint32_t)(((m0 + mi * 16 + arow) * TS + k + acol) * 2);
            LDSM4(ah[mi], uAH + off);
            LDSM4(al[mi], uAL + off);
        }
        uint32_t bh[4][2], bl[4][2];
#pragma unroll
        for (int nq = 0; nq < 2; nq++) {
            uint32_t off = (uint32_t)(((n0 + nq * 16 + brow) * TS + k + bcol) * 2);
            uint32_t r4[4];
            LDSM4(r4, uBH + off);
            bh[2*nq][0]=r4[0]; bh[2*nq][1]=r4[1]; bh[2*nq+1][0]=r4[2]; bh[2*nq+1][1]=r4[3];
            LDSM4(r4, uBL + off);
            bl[2*nq][0]=r4[0]; bl[2*nq][1]=r4[1]; bl[2*nq+1][0]=r4[2]; bl[2*nq+1][1]=r4[3];
        }
#pragma unroll
        for (int mi = 0; mi < 2; mi++)
#pragma unroll
            for (int nj = 0; nj < 4; nj++) {
                MMA(acc[mi][nj], ah[mi], bh[nj]);
                MMA(acc[mi][nj], ah[mi], bl[nj]);
                MMA(acc[mi][nj], al[mi], bh[nj]);
            }
    }
}

// ---------------- fused gi/gh GEMM + GRU, batched over edge type -------------
// grid (ceil(N/64), 3). t = blockIdx.y.
// gi = aggm_t @ F_fused[b,t,s]^T(n-major), gh = m_t @ whh[b,t]^T. GRU -> m_t'.
// SMEM: A1h|A1l|A2h|A2l (4x17408) | WIH|WIL|WHH|WHL (4x34816) = 208896 B.
__global__ void __launch_bounds__(256, 1)
k_gates_b(const bf16* __restrict__ aggmh, const bf16* __restrict__ aggml,
          const bf16* __restrict__ a2hb,  const bf16* __restrict__ a2lb,
          int a2stride,
          const bf16* __restrict__ ffh, const bf16* __restrict__ ffl,   // +(b*9+s)*FW
          const bf16* __restrict__ whhhb, const bf16* __restrict__ whhlb, // +b*3*FW
          const float* __restrict__ bihb, const float* __restrict__ bhhb, // +b*3*G3
          bf16* __restrict__ mh_out, bf16* __restrict__ ml_out) {
    extern __shared__ char sm[];
    bf16* A1H = (bf16*)(sm);
    bf16* A1L = (bf16*)(sm + A64_BYTES);
    bf16* A2H = (bf16*)(sm + 2 * A64_BYTES);
    bf16* A2L = (bf16*)(sm + 3 * A64_BYTES);
    bf16* WIH = (bf16*)(sm + 4 * A64_BYTES);
    bf16* WIL = (bf16*)(sm + 4 * A64_BYTES + MAT_BYTES);
    bf16* WHH = (bf16*)(sm + 4 * A64_BYTES + 2 * MAT_BYTES);
    bf16* WHL = (bf16*)(sm + 4 * A64_BYTES + 3 * MAT_BYTES);

    const int tid  = threadIdx.x;
    const int row0 = blockIdx.x * 64;
    const int t    = blockIdx.y;

    const bf16* A1hG = aggmh + (size_t)t * NC;
    const bf16* A1lG = aggml + (size_t)t * NC;
    const bf16* A2hG = a2hb + (size_t)t * a2stride;
    const bf16* A2lG = a2lb + (size_t)t * a2stride;
    const bf16* BIH = ffh + (size_t)t * 3 * FW;
    const bf16* BIL = ffl + (size_t)t * 3 * FW;
    const bf16* BHH = whhhb + (size_t)t * FW;
    const bf16* BHL = whhlb + (size_t)t * FW;
    const float* bih = bihb + t * G3;
    const float* bhh = bhhb + t * G3;
    bf16* mho = mh_out + (size_t)t * NC;
    bf16* mlo = ml_out + (size_t)t * NC;

    // stage A1, A2 (hi/lo)
#pragma unroll
    for (int i = 0; i < 4; i++) {
        int g = tid + i * 256;
        int r = g >> 4, k8 = (g & 15) * 8;
        uint4 v1h = make_uint4(0,0,0,0), v1l = v1h, v2h = v1h, v2l = v1h;
        if (row0 + r < N_NODES) {
            size_t o = (size_t)(row0 + r) * C + k8;
            v1h = *(const uint4*)(A1hG + o);
            v1l = *(const uint4*)(A1lG + o);
            v2h = *(const uint4*)(A2hG + o);
            v2l = *(const uint4*)(A2lG + o);
        }
        int so = r * TS + k8;
        *(uint4*)(A1H + so) = v1h;
        *(uint4*)(A1L + so) = v1l;
        *(uint4*)(A2H + so) = v2h;
        *(uint4*)(A2L + so) = v2l;
    }

    const int wid  = tid >> 5, lane = tid & 31;
    const int m0 = (wid & 1) * 32;        // 2 m-warps
    const int n0 = (wid >> 1) * 32;       // 4 n-warps
    const uint32_t uA1H = smem_u32(A1H), uA1L = smem_u32(A1L);
    const uint32_t uA2H = smem_u32(A2H), uA2L = smem_u32(A2L);
    const uint32_t uWIH = smem_u32(WIH), uWIL = smem_u32(WIL);
    const uint32_t uWHH = smem_u32(WHH), uWHL = smem_u32(WHL);

    float rg[2][4][4], zg[2][4][4];

#pragma unroll
    for (int blk = 0; blk < 3; blk++) {
        __syncthreads();
        // stage all 4 weight matrices for this 128-col block
#pragma unroll
        for (int i = 0; i < 8; i++) {
            int g = tid + i * 256;
            int n = g >> 4, k8 = (g & 15) * 8;
            size_t o = (size_t)(blk * 128 + n) * C + k8;
            int so = n * TS + k8;
            *(uint4*)(WIH + so) = *(const uint4*)(BIH + o);
            *(uint4*)(WIL + so) = *(const uint4*)(BIL + o);
            *(uint4*)(WHH + so) = *(const uint4*)(BHH + o);
            *(uint4*)(WHL + so) = *(const uint4*)(BHL + o);
        }
        __syncthreads();

        float acc_i[2][4][4], acc_h[2][4][4];
        gemm_tile32(uA1H, uA1L, uWIH, uWIL, m0, n0, lane, acc_i);
        gemm_tile32(uA2H, uA2L, uWHH, uWHL, m0, n0, lane, acc_h);

        if (blk == 0 || blk == 1) {
#pragma unroll
            for (int mi = 0; mi < 2; mi++)
#pragma unroll
                for (int nj = 0; nj < 4; nj++) {
                    int c = blk * 128 + n0 + nj * 8 + (lane & 3) * 2;
                    float bi0 = bih[c], bi1 = bih[c + 1];
                    float bh0 = bhh[c], bh1 = bhh[c + 1];
#pragma unroll
                    for (int q = 0; q < 4; q++) {
                        float pre = acc_i[mi][nj][q] + ((q & 1) ? bi1 : bi0)
                                  + acc_h[mi][nj][q] + ((q & 1) ? bh1 : bh0);
                        float gv = 1.f / (1.f + __expf(-pre));
                        if (blk == 0) rg[mi][nj][q] = gv;
                        else          zg[mi][nj][q] = gv;
                    }
                }
        } else {
#pragma unroll
            for (int mi = 0; mi < 2; mi++)
#pragma unroll
                for (int nj = 0; nj < 4; nj++) {
                    int mc = n0 + nj * 8 + (lane & 3) * 2;
                    int c = 256 + mc;
                    float bi0 = bih[c], bi1 = bih[c + 1];
                    float bh0 = bhh[c], bh1 = bhh[c + 1];
                    float o2[4];
#pragma unroll
                    for (int q = 0; q < 4; q++) {
                        int rl = m0 + mi * 16 + (lane >> 2) + (q >> 1) * 8;
                        int cc = mc + (q & 1);
                        float pi = acc_i[mi][nj][q] + ((q & 1) ? bi1 : bi0);
                        float phv = acc_h[mi][nj][q] + ((q & 1) ? bh1 : bh0);
                        float n = tanhf(pi + rg[mi][nj][q] * phv);
                        float z = zg[mi][nj][q];
                        float mv = __bfloat162float(A2H[rl * TS + cc])
                                 + __bfloat162float(A2L[rl * TS + cc]);
                        o2[q] = (1.f - z) * n + z * mv;
                    }
#pragma unroll
                    for (int h2 = 0; h2 < 2; h2++) {
                        int gr = row0 + m0 + mi * 16 + (lane >> 2) + h2 * 8;
                        if (gr >= N_NODES) continue;
                        float v0 = o2[h2 * 2], v1 = o2[h2 * 2 + 1];
                        bf16 h0, l0, h1, l1;
                        split1(v0, h0, l0); split1(v1, h1, l1);
                        bf162 ph2; ph2.x = h0; ph2.y = h1;
                        bf162 pl2; pl2.x = l0; pl2.y = l1;
                        size_t go = (size_t)gr * C + mc;
                        *(bf162*)(mho + go) = ph2;
                        *(bf162*)(mlo + go) = pl2;
                    }
                }
        }
    }
}

// ---------------- F = conv_w @ wih^T  (per w = (b*3+t)*3+s) ------------------
// grid (3, 18): col-block, w. A = conv_w[w] [k][j] hi/lo, B = wih[bt] [n][j].
__global__ void __launch_bounds__(256, 1)
k_fuse(const bf16* __restrict__ cwh, const bf16* __restrict__ cwl,
       const bf16* __restrict__ wihh, const bf16* __restrict__ wihl,
       float* __restrict__ F) {
    extern __shared__ char sm[];
    bf16* AH = (bf16*)(sm);
    bf16* AL = (bf16*)(sm + MAT_BYTES);
    bf16* BH = (bf16*)(sm + 2 * MAT_BYTES);
    bf16* BL = (bf16*)(sm + 3 * MAT_BYTES);

    const int tid  = threadIdx.x;
    const int col0 = blockIdx.x * 128;
    const int w    = blockIdx.y;
    const int bt   = w / 3;
    const bf16* Ah = cwh + (size_t)w * CW;
    const bf16* Al = cwl + (size_t)w * CW;
    const bf16* Wh = wihh + (size_t)bt * FW + (size_t)col0 * C;
    const bf16* Wl = wihl + (size_t)bt * FW + (size_t)col0 * C;
    float* Y = F + (size_t)w * FW;

#pragma unroll
    for (int i = 0; i < 8; i++) {
        int g = tid + i * 256;
        int r = g >> 4, k8 = (g & 15) * 8;
        *(uint4*)(AH + r * TS + k8) = *(const uint4*)(Ah + (size_t)r * C + k8);
        *(uint4*)(AL + r * TS + k8) = *(const uint4*)(Al + (size_t)r * C + k8);
        *(uint4*)(BH + r * TS + k8) = *(const uint4*)(Wh + (size_t)r * C + k8);
        *(uint4*)(BL + r * TS + k8) = *(const uint4*)(Wl + (size_t)r * C + k8);
    }
    __syncthreads();

    const int wid  = tid >> 5, lane = tid & 31;
    const int m0 = (wid & 3) * 32;
    const int n0 = (wid >> 2) * 64;
    const int arow = lane & 15;
    const int acol = (lane >> 4) << 3;
    const int brow = (lane & 7) + ((lane >> 4) << 3);
    const int bcol = ((lane >> 3) & 1) << 3;
    const uint32_t uAH = smem_u32(AH), uAL = smem_u32(AL);
    const uint32_t uBH = smem_u32(BH), uBL = smem_u32(BL);

    float acc[2][8][4];
#pragma unroll
    for (int mi = 0; mi < 2; mi++)
#pragma unroll
        for (int nj = 0; nj < 8; nj++)
#pragma unroll
            for (int q = 0; q < 4; q++) acc[mi][nj][q] = 0.f;

#pragma unroll
    for (int ks = 0; ks < 8; ks++) {
        const int k = ks * 16;
        uint32_t ah[2][4], al[2][4];
#pragma unroll
        for (int mi = 0; mi < 2; mi++) {
            uint32_t off = (uint32_t)(((m0 + mi * 16 + arow) * TS + k + acol) * 2);
            LDSM4(ah[mi], uAH + off);
            LDSM4(al[mi], uAL + off);
        }
        uint32_t bh[8][2], bl[8][2];
#pragma unroll
        for (int nq = 0; nq < 4; nq++) {
            uint32_t off = (uint32_t)(((n0 + nq * 16 + brow) * TS + k + bcol) * 2);
            uint32_t r4[4];
            LDSM4(r4, uBH + off);
            bh[2*nq][0]=r4[0]; bh[2*nq][1]=r4[1]; bh[2*nq+1][0]=r4[2]; bh[2*nq+1][1]=r4[3];
            LDSM4(r4, uBL + off);
            bl[2*nq][0]=r4[0]; bl[2*nq][1]=r4[1]; bl[2*nq+1][0]=r4[2]; bl[2*nq+1][1]=r4[3];
        }
#pragma unroll
        for (int mi = 0; mi < 2; mi++)
#pragma unroll
            for (int nj = 0; nj < 8; nj++) {
                MMA(acc[mi][nj], ah[mi], bh[nj]);
                MMA(acc[mi][nj], ah[mi], bl[nj]);
                MMA(acc[mi][nj], al[mi], bh[nj]);
            }
    }

    const int rbase = m0 + (lane >> 2);
    const int cbase = n0 + (lane & 3) * 2;
#pragma unroll
    for (int mi = 0; mi < 2; mi++)
#pragma unroll
        for (int nj = 0; nj < 8; nj++) {
            int gr = rbase + mi * 16;
            int gc = col0 + cbase + nj * 8;
            *(float2*)(Y + (size_t)gr * G3 + gc) =
                make_float2(acc[mi][nj][0], acc[mi][nj][1]);
            *(float2*)(Y + (size_t)(gr + 8) * G3 + gc) =
                make_float2(acc[mi][nj][2], acc[mi][nj][3]);
        }
}

// F [w][k][n] -> Ff [w][n][k] hi/lo
__global__ void k_cvt_trF(const float* __restrict__ F, bf16* __restrict__ oh,
                          bf16* __restrict__ ol) {
    int idx = blockIdx.x * 256 + threadIdx.x;
    if (idx >= 18 * FW) return;
    int w = idx / FW, r = idx % FW;
    int n = r >> 7, k = r & 127;
    float v = F[(size_t)w * FW + (size_t)k * G3 + n];
    bf16 h, l; split1(v, h, l);
    oh[idx] = h; ol[idx] = l;
}

// ---------------- weight split -----------------------------------------------
__global__ void k_cvtpair(const float* __restrict__ in, bf16* __restrict__ oh,
                          bf16* __restrict__ ol, int n) {
    int i = blockIdx.x * 256 + threadIdx.x;
    if (i >= n) return;
    bf16 h, l; split1(in[i], h, l);
    oh[i] = h; ol[i] = l;
}

// ---------------- CSR build --------------------------------------------------
__global__ void k_izero(int* __restrict__ p, int n) {
    int i = blockIdx.x * 256 + threadIdx.x;
    if (i < n) p[i] = 0;
}
__global__ void k_count(const int* __restrict__ ei, const int* __restrict__ et,
                        int* __restrict__ cnt) {
    int e = blockIdx.x * 256 + threadIdx.x;
    if (e >= N_EDGES) return;
    atomicAdd(cnt + et[e] * N_NODES + ei[N_EDGES + e], 1);
}
__global__ void k_scan1(const int* __restrict__ cnt, int* __restrict__ incl,
                        int* __restrict__ bsum) {
    __shared__ int sm[1024];
    int i = blockIdx.x * 1024 + threadIdx.x;
    int v = (i < M3) ? cnt[i] : 0;
    sm[threadIdx.x] = v;
    __syncthreads();
#pragma unroll
    for (int off = 1; off < 1024; off <<= 1) {
        int t = (threadIdx.x >= off) ? sm[threadIdx.x - off] : 0;
        __syncthreads();
        sm[threadIdx.x] += t;
        __syncthreads();
    }
    if (i < M3) incl[i] = sm[threadIdx.x];
    if (threadIdx.x == 1023) bsum[blockIdx.x] = sm[1023];
}
__global__ void k_scan2(int* __restrict__ bsum, int nb) {
    if (blockIdx.x == 0 && threadIdx.x == 0) {
        int acc = 0;
        for (int b = 0; b < nb; b++) { int v = bsum[b]; bsum[b] = acc; acc += v; }
    }
}
__global__ void k_scan3(const int* __restrict__ incl, const int* __restrict__ bsum,
                        int* __restrict__ indptr) {
    int i = blockIdx.x * 1024 + threadIdx.x;
    if (i < M3) indptr[i + 1] = incl[i] + bsum[blockIdx.x];
    if (i == 0) indptr[0] = 0;
}
__global__ void k_curinit(const int* __restrict__ indptr, int* __restrict__ cur) {
    int i = blockIdx.x * 256 + threadIdx.x;
    if (i < M3) cur[i] = indptr[i];
}
__global__ void k_fill(const int* __restrict__ ei, const int* __restrict__ et,
                       int* __restrict__ cur, int* __restrict__ eidx) {
    int e = blockIdx.x * 256 + threadIdx.x;
    if (e >= N_EDGES) return;
    int tn = et[e] * N_NODES + ei[N_EDGES + e];
    int p = atomicAdd(cur + tn, 1);
    eidx[p] = ei[e];
}

// ---------------- gather (batched over type): aggm_t[dst] = sum m_t[src] -----
__global__ void k_gather3(const bf16* __restrict__ srch, const bf16* __restrict__ srcl,
                          int sstride,
                          const int* __restrict__ eidx, const int* __restrict__ indptr,
                          bf16* __restrict__ aggh, bf16* __restrict__ aggl) {
    int w = blockIdx.x * 8 + (threadIdx.x >> 5);
    int lane = threadIdx.x & 31;
    int t = blockIdx.y;
    if (w >= N_NODES) return;
    const bf16* mh = srch + (size_t)t * sstride;
    const bf16* ml = srcl + (size_t)t * sstride;
    int tn = t * N_NODES + w;
    int beg = indptr[tn], end = indptr[tn + 1];
    float4 s = make_float4(0.f, 0.f, 0.f, 0.f);
    for (int j = beg; j < end; j++) {
        int src = eidx[j];
        size_t o = (size_t)src * C + lane * 4;
        bf162 h0 = *(const bf162*)(mh + o);
        bf162 h1 = *(const bf162*)(mh + o + 2);
        bf162 l0 = *(const bf162*)(ml + o);
        bf162 l1 = *(const bf162*)(ml + o + 2);
        float2 fh0 = __bfloat1622float2(h0), fh1 = __bfloat1622float2(h1);
        float2 fl0 = __bfloat1622float2(l0), fl1 = __bfloat1622float2(l1);
        s.x += fh0.x + fl0.x; s.y += fh0.y + fl0.y;
        s.z += fh1.x + fl1.x; s.w += fh1.y + fl1.y;
    }
    bf16 hx, lx, hy, ly, hz, lz, hw, lw;
    split1(s.x, hx, lx); split1(s.y, hy, ly);
    split1(s.z, hz, lz); split1(s.w, hw, lw);
    bf162 h01; h01.x = hx; h01.y = hy;
    bf162 h23; h23.x = hz; h23.y = hw;
    bf162 l01; l01.x = lx; l01.y = ly;
    bf162 l23; l23.x = lz; l23.y = lw;
    size_t o = (size_t)t * NC + (size_t)w * C + lane * 4;
    *(bf162*)(aggh + o)     = h01;
    *(bf162*)(aggh + o + 2) = h23;
    *(bf162*)(aggl + o)     = l01;
    *(bf162*)(aggl + o + 2) = l23;
}

// ---------------- head GEMM (128-row tile) -----------------------------------
__global__ void __launch_bounds__(256, 1)
k_mma2(const bf16* __restrict__ Ah, const bf16* __restrict__ Al,
       const bf16* __restrict__ Wh, const bf16* __restrict__ Wl,
       const float* __restrict__ bias, float* __restrict__ Y) {
    extern __shared__ char sm[];
    bf16* AH = (bf16*)(sm);
    bf16* AL = (bf16*)(sm + MAT_BYTES);
    bf16* BH = (bf16*)(sm + 2 * MAT_BYTES);
    bf16* BL = (bf16*)(sm + 3 * MAT_BYTES);

    const int tid  = threadIdx.x;
    const int row0 = blockIdx.x * 128;

#pragma unroll
    for (int i = 0; i < 8; i++) {
        int g = tid + i * 256;
        int r = g >> 4, k8 = (g & 15) * 8;
        uint4 vh = make_uint4(0u, 0u, 0u, 0u), vl = vh;
        if (row0 + r < N_NODES) {
            vh = *(const uint4*)(Ah + (size_t)(row0 + r) * C + k8);
            vl = *(const uint4*)(Al + (size_t)(row0 + r) * C + k8);
        }
        *(uint4*)(AH + r * TS + k8) = vh;
        *(uint4*)(AL + r * TS + k8) = vl;
        *(uint4*)(BH + r * TS + k8) = *(const uint4*)(Wh + (size_t)r * C + k8);
        *(uint4*)(BL + r * TS + k8) = *(const uint4*)(Wl + (size_t)r * C + k8);
    }
    __syncthreads();

    const int wid  = tid >> 5, lane = tid & 31;
    const int m0 = (wid & 3) * 32;
    const int n0 = (wid >> 2) * 64;
    const int arow = lane & 15;
    const int acol = (lane >> 4) << 3;
    const int brow = (lane & 7) + ((lane >> 4) << 3);
    const int bcol = ((lane >> 3) & 1) << 3;
    const uint32_t uAH = smem_u32(AH), uAL = smem_u32(AL);
    const uint32_t uBH = smem_u32(BH), uBL = smem_u32(BL);

    float acc[2][8][4];
#pragma unroll
    for (int mi = 0; mi < 2; mi++)
#pragma unroll
        for (int nj = 0; nj < 8; nj++)
#pragma unroll
            for (int q = 0; q < 4; q++) acc[mi][nj][q] = 0.f;

#pragma unroll
    for (int ks = 0; ks < 8; ks++) {
        const int k = ks * 16;
        uint32_t ah[2][4], al[2][4];
#pragma unroll
        for (int mi = 0; mi < 2; mi++) {
            uint32_t off = (uint32_t)(((m0 + mi * 16 + arow) * TS + k + acol) * 2);
            LDSM4(ah[mi], uAH + off);
            LDSM4(al[mi], uAL + off);
        }
        uint32_t bh[8][2], bl[8][2];
#pragma unroll
        for (int nq = 0; nq < 4; nq++) {
            uint32_t off = (uint32_t)(((n0 + nq * 16 + brow) * TS + k + bcol) * 2);
            uint32_t r4[4];
            LDSM4(r4, uBH + off);
            bh[2*nq][0]=r4[0]; bh[2*nq][1]=r4[1]; bh[2*nq+1][0]=r4[2]; bh[2*nq+1][1]=r4[3];
            LDSM4(r4, uBL + off);
            bl[2*nq][0]=r4[0]; bl[2*nq][1]=r4[1]; bl[2*nq+1][0]=r4[2]; bl[2*nq+1][1]=r4[3];
        }
#pragma unroll
        for (int mi = 0; mi < 2; mi++)
#pragma unroll
            for (int nj = 0; nj < 8; nj++) {
                MMA(acc[mi][nj], ah[mi], bh[nj]);
                MMA(acc[mi][nj], ah[mi], bl[nj]);
                MMA(acc[mi][nj], al[mi], bh[nj]);
            }
    }

    const int rbase = row0 + m0 + (lane >> 2);
    const int cbase = n0 + (lane & 3) * 2;
#pragma unroll
    for (int mi = 0; mi < 2; mi++)
#pragma unroll
        for (int nj = 0; nj < 8; nj++) {
            int gr = rbase + mi * 16;
            int gc = cbase + nj * 8;
            float b0 = bias[gc], b1 = bias[gc + 1];
            float2 v0, v1;
            v0.x = fmaxf(acc[mi][nj][0] + b0, 0.f);
            v0.y = fmaxf(acc[mi][nj][1] + b1, 0.f);
            v1.x = fmaxf(acc[mi][nj][2] + b0, 0.f);
            v1.y = fmaxf(acc[mi][nj][3] + b1, 0.f);
            if (gr < N_NODES)
                *(float2*)(Y + (size_t)gr * C + gc) = v0;
            if (gr + 8 < N_NODES)
                *(float2*)(Y + (size_t)(gr + 8) * C + gc) = v1;
        }
}

// ---------------- feature build ----------------------------------------------
__global__ void k_feat(const int* __restrict__ xt, const int* __restrict__ xk,
                       const float* __restrict__ xs, float* __restrict__ h,
                       bf16* __restrict__ hh, bf16* __restrict__ hl) {
    int i = blockIdx.x;
    int c = threadIdx.x;
    int t = xt[i];
    int k = xk[i];
    k = min(max(k, 0), 93);
    float v;
    if (c < 32)       v = (c == t) ? 1.f : 0.f;
    else if (c < 126) v = ((c - 32) == k) ? 1.f : 0.f;
    else              v = xs[i * 2 + (c - 126)];
    size_t o = (size_t)i * C + c;
    h[o] = v;
    bf16 bh, bl; split1(v, bh, bl);
    hh[o] = bh; hl[o] = bl;
}

// ---------------- LayerNorm(h + sum_t m_t)*g+b, ReLU -------------------------
__global__ void k_ln(float* __restrict__ h, const bf16* __restrict__ mh,
                     const bf16* __restrict__ ml,
                     const float* __restrict__ g, const float* __restrict__ b,
                     bf16* __restrict__ hh, bf16* __restrict__ hl) {
    int i = blockIdx.x * 8 + (threadIdx.x >> 5);
    int lane = threadIdx.x & 31;
    if (i >= N_NODES) return;
    size_t o4 = (size_t)i * C + lane * 4;
    float4 v = ((float4*)(h + (size_t)i * C))[lane];
#pragma unroll
    for (int t = 0; t < 3; t++) {
        size_t o = (size_t)t * NC + o4;
        bf162 h0 = *(const bf162*)(mh + o);
        bf162 h1 = *(const bf162*)(mh + o + 2);
        bf162 l0 = *(const bf162*)(ml + o);
        bf162 l1 = *(const bf162*)(ml + o + 2);
        float2 fh0 = __bfloat1622float2(h0), fh1 = __bfloat1622float2(h1);
        float2 fl0 = __bfloat1622float2(l0), fl1 = __bfloat1622float2(l1);
        v.x += fh0.x + fl0.x; v.y += fh0.y + fl0.y;
        v.z += fh1.x + fl1.x; v.w += fh1.y + fl1.y;
    }
    float s  = v.x + v.y + v.z + v.w;
    float ss = v.x * v.x + v.y * v.y + v.z * v.z + v.w * v.w;
#pragma unroll
    for (int off = 16; off; off >>= 1) {
        s  += __shfl_xor_sync(0xffffffffu, s, off);
        ss += __shfl_xor_sync(0xffffffffu, ss, off);
    }
    float mu  = s * (1.f / 128.f);
    float var = ss * (1.f / 128.f) - mu * mu;
    float inv = rsqrtf(var + 1e-5f);
    float4 gg = ((const float4*)g)[lane];
    float4 bb = ((const float4*)b)[lane];
    float4 o;
    o.x = fmaxf((v.x - mu) * inv * gg.x + bb.x, 0.f);
    o.y = fmaxf((v.y - mu) * inv * gg.y + bb.y, 0.f);
    o.z = fmaxf((v.z - mu) * inv * gg.z + bb.z, 0.f);
    o.w = fmaxf((v.w - mu) * inv * gg.w + bb.w, 0.f);
    ((float4*)(h + (size_t)i * C))[lane] = o;
    bf16 hx, lx, hy, ly, hz, lz, hw, lw;
    split1(o.x, hx, lx); split1(o.y, hy, ly);
    split1(o.z, hz, lz); split1(o.w, hw, lw);
    bf162 p01, p23, q01, q23;
    p01.x = hx; p01.y = hy; p23.x = hz; p23.y = hw;
    q01.x = lx; q01.y = ly; q23.x = lz; q23.y = lw;
    *(bf162*)(hh + o4)     = p01;
    *(bf162*)(hh + o4 + 2) = p23;
    *(bf162*)(hl + o4)     = q01;
    *(bf162*)(hl + o4 + 2) = q23;
}

// ---------------- head second layer ------------------------------------------
__global__ void k_head2(const float* __restrict__ z, const float* __restrict__ w2,
                        const float* __restrict__ b2, float* __restrict__ out) {
    int i = blockIdx.x * 8 + (threadIdx.x >> 5);
    int lane = threadIdx.x & 31;
    if (i >= N_NODES) return;
    float4 zv = ((const float4*)(z + (size_t)i * C))[lane];
    float4 w0 = ((const float4*)w2)[lane];
    float4 w1 = ((const float4*)(w2 + C))[lane];
    float d0 = zv.x * w0.x + zv.y * w0.y + zv.z * w0.z + zv.w * w0.w;
    float d1 = zv.x * w1.x + zv.y * w1.y + zv.z * w1.z + zv.w * w1.w;
#pragma unroll
    for (int off = 16; off; off >>= 1) {
        d0 += __shfl_xor_sync(0xffffffffu, d0, off);
        d1 += __shfl_xor_sync(0xffffffffu, d1, off);
    }
    if (lane == 0) {
        out[(size_t)i * 2 + 0] = d0 + b2[0];
        out[(size_t)i * 2 + 1] = d1 + b2[1];
    }
}

// ---------------- driver -----------------------------------------------------
extern "C" void kernel_launch(void* const* d_in, const int* in_sizes, int n_in,
                              void* d_out, int out_size) {
    const int*   x_type     = (const int*)d_in[0];
    const int*   x_tok      = (const int*)d_in[1];
    const float* x_small    = (const float*)d_in[2];
    const int*   edge_index = (const int*)d_in[3];
    const int*   edge_type  = (const int*)d_in[4];
    const float* conv_w     = (const float*)d_in[5];
    const float* gru_wih    = (const float*)d_in[6];
    const float* gru_whh    = (const float*)d_in[7];
    const float* gru_bih    = (const float*)d_in[8];
    const float* gru_bhh    = (const float*)d_in[9];
    const float* ln_g       = (const float*)d_in[10];
    const float* ln_b       = (const float*)d_in[11];
    const float* head_w1    = (const float*)d_in[12];
    const float* head_b1    = (const float*)d_in[13];
    const float* head_w2    = (const float*)d_in[14];
    const float* head_b2    = (const float*)d_in[15];
    float* out = (float*)d_out;

    float *ph, *px, *pF;
    bf16 *phh, *phl, *pmh, *pml, *pah, *pal;
    bf16 *pcwh, *pcwl, *pwihh, *pwihl, *pwhhh, *pwhhl, *pw1h, *pw1l, *pffh, *pffl;
    int *pcnt, *pincl, *pcur, *pbsum, *pindptr, *peidx;
    cudaGetSymbolAddress((void**)&ph,   g_h);
    cudaGetSymbolAddress((void**)&px,   g_x);
    cudaGetSymbolAddress((void**)&pF,   g_F);
    cudaGetSymbolAddress((void**)&phh,  g_hh);
    cudaGetSymbolAddress((void**)&phl,  g_hl);
    cudaGetSymbolAddress((void**)&pmh,  g_mh);
    cudaGetSymbolAddress((void**)&pml,  g_ml);
    cudaGetSymbolAddress((void**)&pah,  g_ah);
    cudaGetSymbolAddress((void**)&pal,  g_al);
    cudaGetSymbolAddress((void**)&pcwh, g_cwh);
    cudaGetSymbolAddress((void**)&pcwl, g_cwl);
    cudaGetSymbolAddress((void**)&pwihh, g_wihh);
    cudaGetSymbolAddress((void**)&pwihl, g_wihl);
    cudaGetSymbolAddress((void**)&pwhhh, g_whhh);
    cudaGetSymbolAddress((void**)&pwhhl, g_whhl);
    cudaGetSymbolAddress((void**)&pw1h, g_w1h);
    cudaGetSymbolAddress((void**)&pw1l, g_w1l);
    cudaGetSymbolAddress((void**)&pffh, g_ffh);
    cudaGetSymbolAddress((void**)&pffl, g_ffl);
    cudaGetSymbolAddress((void**)&pcnt, g_cnt);
    cudaGetSymbolAddress((void**)&pincl, g_incl);
    cudaGetSymbolAddress((void**)&pcur, g_cur);
    cudaGetSymbolAddress((void**)&pbsum, g_bsum);
    cudaGetSymbolAddress((void**)&pindptr, g_indptr);
    cudaGetSymbolAddress((void**)&peidx, g_eidx);

    const int SMEMSZ = 4 * MAT_BYTES;                     // 139264 (k_fuse, head)
    const int GSMEM  = 4 * A64_BYTES + 4 * MAT_BYTES;     // 208896 (gates)
    cudaFuncSetAttribute(k_fuse,
                         cudaFuncAttributeMaxDynamicSharedMemorySize, SMEMSZ);
    cudaFuncSetAttribute(k_mma2,
                         cudaFuncAttributeMaxDynamicSharedMemorySize, SMEMSZ);
    cudaFuncSetAttribute(k_gates_b,
                         cudaFuncAttributeMaxDynamicSharedMemorySize, GSMEM);

    const int rowBlocks = (N_NODES + 127) / 128;    // 391
    const int rowBlocks64 = (N_NODES + 63) / 64;    // 782
    const int warpGrid = (N_NODES + 7) / 8;
    const int SCANB = (M3 + 1023) / 1024;           // 147
    const int EG = (N_EDGES + 255) / 256;

    // ---- one-time: features, weight splits, CSR, fused weights ----
    k_feat<<<N_NODES, 128>>>(x_type, x_tok, x_small, ph, phh, phl);
    k_cvtpair<<<(18*CW + 255)/256, 256>>>(conv_w, pcwh, pcwl, 18*CW);
    k_cvtpair<<<(6*G3*C + 255)/256, 256>>>(gru_wih, pwihh, pwihl, 6*G3*C);
    k_cvtpair<<<(6*G3*C + 255)/256, 256>>>(gru_whh, pwhhh, pwhhl, 6*G3*C);
    k_cvtpair<<<(CW + 255)/256, 256>>>(head_w1, pw1h, pw1l, CW);

    k_izero<<<(M3 + 255)/256, 256>>>(pcnt, M3);
    k_count<<<EG, 256>>>(edge_index, edge_type, pcnt);
    k_scan1<<<SCANB, 1024>>>(pcnt, pincl, pbsum);
    k_scan2<<<1, 32>>>(pbsum, SCANB);
    k_scan3<<<SCANB, 1024>>>(pincl, pbsum, pindptr);
    k_curinit<<<(M3 + 255)/256, 256>>>(pindptr, pcur);
    k_fill<<<EG, 256>>>(edge_index, edge_type, pcur, peidx);

    k_fuse<<<dim3(3, 18), 256, SMEMSZ>>>(pcwh, pcwl, pwihh, pwihl, pF);
    k_cvt_trF<<<(18*FW + 255)/256, 256>>>(pF, pffh, pffl);

    for (int b = 0; b < 2; b++) {
        for (int s = 0; s < 3; s++) {
            const bf16* srch = (s == 0) ? phh : pmh;
            const bf16* srcl = (s == 0) ? phl : pml;
            int stride = (s == 0) ? 0 : NC;
            k_gather3<<<dim3(warpGrid, 3), 256>>>(srch, srcl, stride,
                                                  peidx, pindptr, pah, pal);
            k_gates_b<<<dim3(rowBlocks64, 3), 256, GSMEM>>>(
                pah, pal, srch, srcl, stride,
                pffh + (size_t)(b * 9 + s) * FW, pffl + (size_t)(b * 9 + s) * FW,
                pwhhh + (size_t)b * 3 * FW, pwhhl + (size_t)b * 3 * FW,
                gru_bih + (size_t)b * 3 * G3, gru_bhh + (size_t)b * 3 * G3,
                pmh, pml);
        }
        k_ln<<<warpGrid, 256>>>(ph, pmh, pml, ln_g + b * C, ln_b + b * C, phh, phl);
    }

    // head
    k_mma2<<<rowBlocks, 256, SMEMSZ>>>(phh, phl, pw1h, pw1l, head_b1, px);
    k_head2<<<warpGrid, 256>>>(px, head_w2, head_b2, out);
}